// round 9
// baseline (speedup 1.0000x reference)
#include <cuda_runtime.h>
#include <math.h>
#include <stdint.h>

#define L_Q   1024
#define BSZ   2
#define DIM   1024
#define NHEAD 16
#define DHEAD 64
#define NLAY  4
#define MLEN  1024
#define KLEN  2048
#define NE    (L_Q*BSZ*DIM)   /* 2097152 floats per (L,B,D) slab */

// ---------------- scratch (device globals; no allocation allowed) ----------------
__device__ float g_wheads[(size_t)KLEN*BSZ*3*DIM];   // 50 MB
__device__ float g_pos[(size_t)KLEN*DIM];            // 8 MB
__device__ float g_rhead[(size_t)KLEN*DIM];          // 8 MB
__device__ float g_attnvec[NE];
__device__ float g_tmp[NE];
__device__ float g_core[NE];
__device__ float g_core2[NE];
__device__ float g_ff[NE];

// ---------------- simple float4 copy ----------------
__global__ void copy_kernel(float* __restrict__ dst, const float* __restrict__ src, int n4) {
    int i = blockIdx.x * blockDim.x + threadIdx.x;
    if (i < n4) ((float4*)dst)[i] = ((const float4*)src)[i];
}

// ---------------- positional embedding ----------------
__global__ void pos_kernel(float* __restrict__ pos) {
    int idx = blockIdx.x * blockDim.x + threadIdx.x;
    if (idx >= KLEN * DIM) return;
    int j = idx >> 10;           // 0..2047
    int i = idx & 1023;          // 0..1023
    int t = i & 511;
    float x = (float)(2 * t) * (1.0f / 1024.0f);
    float invf = expf(-x * 9.210340371976184f);   // 10000^{-x}
    float arg = (float)(KLEN - 1 - j) * invf;
    pos[idx] = (i < 512) ? sinf(arg) : cosf(arg);
}

// ---------------- tf32 helpers ----------------
__device__ __forceinline__ uint32_t f2tf32(float f) {
    uint32_t u;
    asm("cvt.rna.tf32.f32 %0, %1;" : "=r"(u) : "f"(f));
    return u;
}
__device__ __forceinline__ uint4 cvt4(float4 v) {
    return make_uint4(f2tf32(v.x), f2tf32(v.y), f2tf32(v.z), f2tf32(v.w));
}
__device__ __forceinline__ void mma_tf32(float* c, const uint32_t* a, const uint32_t* b) {
    asm volatile(
        "mma.sync.aligned.m16n8k8.row.col.f32.tf32.tf32.f32 "
        "{%0,%1,%2,%3}, {%4,%5,%6,%7}, {%8,%9}, {%0,%1,%2,%3};"
        : "+f"(c[0]), "+f"(c[1]), "+f"(c[2]), "+f"(c[3])
        : "r"(a[0]), "r"(a[1]), "r"(a[2]), "r"(a[3]), "r"(b[0]), "r"(b[1]));
}

// ---------------- tf32 tensor-core GEMM: 128x128 block, K-tile 32, 2-stage ----
// Conflict-free staging: remapped thread->element assignment + per-thread STS
// rotation so every staging STS.32 hits 32 distinct banks.
__global__ __launch_bounds__(256) void mma_gemm(
    const float* __restrict__ A, const float* __restrict__ B, float* __restrict__ C,
    int M, int N, int K, int lda, int ldb, int ldc,
    const float* __restrict__ bias, int relu)
{
    __shared__ __align__(16) uint32_t As[2][4096];
    __shared__ __align__(16) uint32_t Bs[2][4096];

    const int tid = threadIdx.x;
    const int lane = tid & 31;
    const int w = tid >> 5;
    const int wr = w & 1;            // 0..1
    const int wc = w >> 1;           // 0..3
    const int bx = blockIdx.x, by = blockIdx.y;

    // ---- A staging map: row = tid>>1, col-half = (tid&1)*4, cols chalf+8*tt+i ----
    const int ar    = tid >> 1;            // 0..127
    const int ach   = tid & 1;             // col base 0 or 4
    const int amb   = ar >> 4;
    const int ag    = ar & 7;
    const int aq    = ((ar >> 3) & 1) + 2 * ach;
    const int arho  = (ar >> 1) & 3;
    const int abase = ((amb * 32 + ag * 4) << 2) + aq;   // + tt*1024 + i*4

    // ---- B staging map: k0 = tid&7 (k = k0+8*tt), n0 = (tid>>3)*4 ----
    const int bk0   = tid & 7;
    const int bng   = tid >> 3;            // 0..31
    const int bn0   = bng << 2;            // 0..124
    const int bkl   = bk0 & 3;
    const int bkq   = bk0 >> 2;
    const int bnb   = bng >> 1;
    const int bnlow = (bng & 1) << 2;      // 0 or 4
    const int brho  = bng & 3;
    const int bbase = ((bnb * 32 + bkl) << 1) + bkq;     // + tt*1024 + (bnlow+i)*8

    const float* Ag = A + (size_t)(by * 128 + ar) * lda + ach * 4;
    const float* Bg = B + (size_t)bk0 * ldb + bx * 128 + bn0;

    float acc[4][4][4];
#pragma unroll
    for (int mi = 0; mi < 4; mi++)
#pragma unroll
        for (int ni = 0; ni < 4; ni++)
#pragma unroll
            for (int q = 0; q < 4; q++) acc[mi][ni][q] = 0.f;

    float4 pa[4], pb[4];
#pragma unroll
    for (int tt = 0; tt < 4; tt++) {
        pa[tt] = *(const float4*)(Ag + tt * 8);
        pb[tt] = *(const float4*)(Bg + (size_t)(tt * 8) * ldb);
    }
    // stage tile 0 -> buf 0 (rotated, conflict-free)
#pragma unroll
    for (int tt = 0; tt < 4; tt++) {
        const float* fa = (const float*)&pa[tt];
        const float* fb = (const float*)&pb[tt];
#pragma unroll
        for (int j = 0; j < 4; j++) {
            const int ia = (j + arho) & 3;
            As[0][tt * 1024 + abase + (ia << 2)] = f2tf32(fa[ia]);
            const int ib = (j + brho) & 3;
            Bs[0][tt * 1024 + bbase + ((bnlow + ib) << 3)] = f2tf32(fb[ib]);
        }
    }
    __syncthreads();

    const int NT = K >> 5;
    for (int T = 0; T < NT; T++) {
        const int buf = T & 1;
        if (T + 1 < NT) {
            const int off = (T + 1) << 5;
#pragma unroll
            for (int tt = 0; tt < 4; tt++) {
                pa[tt] = *(const float4*)(Ag + off + tt * 8);
                pb[tt] = *(const float4*)(Bg + (size_t)(off + tt * 8) * ldb);
            }
        }
#pragma unroll
        for (int ks = 0; ks < 4; ks++) {
            uint32_t afr[4][4], bfr[4][2];
#pragma unroll
            for (int mi = 0; mi < 4; mi++) {
                const uint4 v = *(const uint4*)&As[buf][(((ks * 8 + wr * 4 + mi) * 32 + lane) << 2)];
                afr[mi][0] = v.x; afr[mi][1] = v.y; afr[mi][2] = v.z; afr[mi][3] = v.w;
            }
#pragma unroll
            for (int ni = 0; ni < 4; ni++) {
                const uint2 v = *(const uint2*)&Bs[buf][(((ks * 16 + wc * 4 + ni) * 32 + lane) << 1)];
                bfr[ni][0] = v.x; bfr[ni][1] = v.y;
            }
#pragma unroll
            for (int mi = 0; mi < 4; mi++)
#pragma unroll
                for (int ni = 0; ni < 4; ni++)
                    mma_tf32(acc[mi][ni], afr[mi], bfr[ni]);
        }
        if (T + 1 < NT) {
            const int nb2 = buf ^ 1;
#pragma unroll
            for (int tt = 0; tt < 4; tt++) {
                const float* fa = (const float*)&pa[tt];
                const float* fb = (const float*)&pb[tt];
#pragma unroll
                for (int j = 0; j < 4; j++) {
                    const int ia = (j + arho) & 3;
                    As[nb2][tt * 1024 + abase + (ia << 2)] = f2tf32(fa[ia]);
                    const int ib = (j + brho) & 3;
                    Bs[nb2][tt * 1024 + bbase + ((bnlow + ib) << 3)] = f2tf32(fb[ib]);
                }
            }
        }
        __syncthreads();
    }

    const int g = lane >> 2;
    const int t = lane & 3;
#pragma unroll
    for (int mi = 0; mi < 4; mi++) {
        const int r0 = by * 128 + wr * 64 + mi * 16 + g;
#pragma unroll
        for (int ni = 0; ni < 4; ni++) {
            const int c0 = bx * 128 + wc * 32 + ni * 8 + t * 2;
            float b0 = 0.f, b1 = 0.f;
            if (bias) { b0 = bias[c0]; b1 = bias[c0 + 1]; }
            float2 o0, o1;
            o0.x = acc[mi][ni][0] + b0; o0.y = acc[mi][ni][1] + b1;
            o1.x = acc[mi][ni][2] + b0; o1.y = acc[mi][ni][3] + b1;
            if (relu) {
                o0.x = fmaxf(o0.x, 0.f); o0.y = fmaxf(o0.y, 0.f);
                o1.x = fmaxf(o1.x, 0.f); o1.y = fmaxf(o1.y, 0.f);
            }
            *(float2*)&C[(size_t)r0 * ldc + c0] = o0;
            *(float2*)&C[(size_t)(r0 + 8) * ldc + c0] = o1;
        }
    }
}

// ---------------- tensor-core fused rel-attention (pitch-68 + E-band skip) ----
#define AT_QW 0                     /* 64x68 tf32 */
#define AT_QR 4352
#define AT_K  8704
#define AT_R  13056                 /* 128x68 (127 used) */
#define AT_V  21760
#define AT_S  26112                 /* 64x68 f32 */
#define AT_E  30464                 /* 64x136 f32 */
#define AT_P  39168                 /* 64x68 tf32 */
#define AT_M  43520
#define AT_L  43584
#define AT_A  43648
#define ATTN2_SMEM_FLOATS 43712
#define ATTN2_SMEM_BYTES  (ATTN2_SMEM_FLOATS * 4)

__global__ __launch_bounds__(256) void attn_mma_kernel(
    const float* __restrict__ wh, const float* __restrict__ rh,
    const float* __restrict__ rwb, const float* __restrict__ rrb,
    float* __restrict__ av)
{
    extern __shared__ float smf[];
    uint32_t* sQw = (uint32_t*)(smf + AT_QW);
    uint32_t* sQr = (uint32_t*)(smf + AT_QR);
    uint32_t* sK  = (uint32_t*)(smf + AT_K);
    uint32_t* sR  = (uint32_t*)(smf + AT_R);
    uint32_t* sV  = (uint32_t*)(smf + AT_V);
    float*    sS  = smf + AT_S;
    float*    sE  = smf + AT_E;
    uint32_t* sP  = (uint32_t*)(smf + AT_P);
    float*    sM  = smf + AT_M;
    float*    sL  = smf + AT_L;
    float*    sA  = smf + AT_A;

    const int i0 = (15 - blockIdx.x) << 6;   // heaviest q-tile first
    const int bi = blockIdx.y >> 4;
    const int hn = blockIdx.y & 15;
    const int tid = threadIdx.x;
    const int lane = tid & 31;
    const int w = tid >> 5;
    const int rb = w >> 1;           // 0..3
    const int ch = w & 1;            // 0..1
    const int g = lane >> 2;         // 0..7
    const int t = lane & 3;          // 0..3
    const int hbase = hn << 6;

    // E diagonal-band block bounds for this warp (rows 16rb..16rb+15, col half ch)
    int ebmin = 41 - 16 * rb - 64 * ch;
    ebmin = ebmin <= 0 ? 0 : ((ebmin + 7) >> 3);
    int ebmax = (126 - 16 * rb - 64 * ch) >> 3;
    if (ebmax > 7) ebmax = 7;

    // staging lane coords (float4 granularity)
    const int svr = tid >> 4;             // row 0..15 base (of 64, via +u*16)
    const int svc = (tid & 15) << 2;      // col 0,4,..,60

    // ---- load Q tiles (bias folded), vectorized ----
    {
        float4 w4 = *(const float4*)&rwb[hbase + svc];
        float4 r4 = *(const float4*)&rrb[hbase + svc];
#pragma unroll
        for (int u = 0; u < 4; u++) {
            const int r = svr + u * 16;
            const size_t base = ((size_t)((MLEN + i0 + r) * BSZ + bi)) * 3072 + hbase + svc;
            float4 q4 = *(const float4*)&wh[base];
            float4 aw = make_float4(q4.x + w4.x, q4.y + w4.y, q4.z + w4.z, q4.w + w4.w);
            float4 ar = make_float4(q4.x + r4.x, q4.y + r4.y, q4.z + r4.z, q4.w + r4.w);
            *(uint4*)&sQw[r * 68 + svc] = cvt4(aw);
            *(uint4*)&sQr[r * 68 + svc] = cvt4(ar);
        }
    }
    if (tid < 64) { sM[tid] = -3e38f; sL[tid] = 0.f; }

    float acc[4][4];   // PV accum frags
#pragma unroll
    for (int cb = 0; cb < 4; cb++)
#pragma unroll
        for (int q = 0; q < 4; q++) acc[cb][q] = 0.f;

    const int arow0 = (16 * rb + g) * 68;
    const int arow1 = (16 * rb + g + 8) * 68;
    const int nkt = 17 + (i0 >> 6);

    // K/V prefetch registers for tile 0
    float4 pk[4], pv[4];
#pragma unroll
    for (int u = 0; u < 4; u++) {
        const int r = svr + u * 16;
        const size_t base = ((size_t)(r * BSZ + bi)) * 3072 + hbase + svc;
        pk[u] = *(const float4*)&wh[base + 1024];
        pv[u] = *(const float4*)&wh[base + 2048];
    }

    for (int kt = 0; kt < nkt; kt++) {
        const int j0 = kt << 6;
        __syncthreads();
        // ---- store prefetched K/V; stage R directly ----
#pragma unroll
        for (int u = 0; u < 4; u++) {
            const int r = svr + u * 16;
            *(uint4*)&sK[r * 68 + svc] = cvt4(pk[u]);
            *(uint4*)&sV[r * 68 + svc] = cvt4(pv[u]);
        }
        const int rbase = j0 + MLEN - 1 - i0 - 63;
#pragma unroll
        for (int u = 0; u < 8; u++) {
            const int idx = tid + u * 256;
            if (idx < 2032) {
                const int r = idx >> 4, c4 = (idx & 15) << 2;
                int rg = rbase + r;
                rg = rg < 0 ? 0 : (rg > KLEN - 1 ? KLEN - 1 : rg);
                const float4 v = *(const float4*)&rh[(size_t)rg * DIM + hbase + c4];
                *(uint4*)&sR[r * 68 + c4] = cvt4(v);
            }
        }
        __syncthreads();

        // ---- prefetch next tile's K/V (overlaps mma below) ----
        if (kt + 1 < nkt) {
#pragma unroll
            for (int u = 0; u < 4; u++) {
                const int r = svr + u * 16;
                const size_t base = ((size_t)(((j0 + 64) + r) * BSZ + bi)) * 3072 + hbase + svc;
                pk[u] = *(const float4*)&wh[base + 1024];
                pv[u] = *(const float4*)&wh[base + 2048];
            }
        }

        // ---- S and E via mma (E restricted to diagonal band blocks) ----
        float Sacc[4][4], Eacc[8][4];
#pragma unroll
        for (int cb = 0; cb < 4; cb++)
#pragma unroll
            for (int q = 0; q < 4; q++) Sacc[cb][q] = 0.f;
#pragma unroll
        for (int eb = 0; eb < 8; eb++)
#pragma unroll
            for (int q = 0; q < 4; q++) Eacc[eb][q] = 0.f;

#pragma unroll
        for (int ks = 0; ks < 8; ks++) {
            const int kc = ks * 8 + t;
            uint32_t aw[4], ar[4];
            aw[0] = sQw[arow0 + kc]; aw[1] = sQw[arow1 + kc];
            aw[2] = sQw[arow0 + kc + 4]; aw[3] = sQw[arow1 + kc + 4];
            ar[0] = sQr[arow0 + kc]; ar[1] = sQr[arow1 + kc];
            ar[2] = sQr[arow0 + kc + 4]; ar[3] = sQr[arow1 + kc + 4];
#pragma unroll
            for (int cb = 0; cb < 4; cb++) {
                const int kr = (8 * (ch * 4 + cb) + g) * 68 + kc;
                uint32_t b[2] = { sK[kr], sK[kr + 4] };
                mma_tf32(Sacc[cb], aw, b);
            }
#pragma unroll
            for (int eb = 0; eb < 8; eb++) {
                if (eb >= ebmin && eb <= ebmax) {
                    const int rr = (8 * (ch * 8 + eb) + g) * 68 + kc;
                    uint32_t b[2] = { sR[rr], sR[rr + 4] };
                    mma_tf32(Eacc[eb], ar, b);
                }
            }
        }
        // write S, E to smem (float2 stores)
#pragma unroll
        for (int cb = 0; cb < 4; cb++) {
            const int col = 8 * (ch * 4 + cb) + 2 * t;
            *(float2*)&sS[(16 * rb + g) * 68 + col]     = make_float2(Sacc[cb][0], Sacc[cb][1]);
            *(float2*)&sS[(16 * rb + g + 8) * 68 + col] = make_float2(Sacc[cb][2], Sacc[cb][3]);
        }
#pragma unroll
        for (int eb = 0; eb < 8; eb++) {
            if (eb >= ebmin && eb <= ebmax) {
                const int col = 8 * (ch * 8 + eb) + 2 * t;
                *(float2*)&sE[(16 * rb + g) * 136 + col]     = make_float2(Eacc[eb][0], Eacc[eb][1]);
                *(float2*)&sE[(16 * rb + g + 8) * 136 + col] = make_float2(Eacc[eb][2], Eacc[eb][3]);
            }
        }
        __syncthreads();

        // ---- online softmax: warp w owns rows w*8..w*8+7; lane quad per row ----
        {
            const int row = w * 8 + g;
            const int qi = i0 + row;
            float sarr[16];
            {
                const float4* srow = (const float4*)&sS[row * 68 + t * 16];
#pragma unroll
                for (int v4 = 0; v4 < 4; v4++) {
                    float4 s4 = srow[v4];
                    sarr[v4 * 4 + 0] = s4.x; sarr[v4 * 4 + 1] = s4.y;
                    sarr[v4 * 4 + 2] = s4.z; sarr[v4 * 4 + 3] = s4.w;
                }
            }
            const int ebase = row * 135 + t * 16 + 63;   // row*136 + (t*16 - row + 63)
            float tmax = -3e38f;
#pragma unroll
            for (int e = 0; e < 16; e++) {
                float vv = (sarr[e] + sE[ebase + e]) * 0.125f;
                if (j0 + t * 16 + e > MLEN + qi) vv = -3e38f;
                sarr[e] = vv;
                tmax = fmaxf(tmax, vv);
            }
            tmax = fmaxf(tmax, __shfl_xor_sync(0xffffffffu, tmax, 1));
            tmax = fmaxf(tmax, __shfl_xor_sync(0xffffffffu, tmax, 2));
            const float mold = sM[row];
            const float mnew = fmaxf(mold, tmax);
            float rsum = 0.f;
            uint32_t pb[16];
#pragma unroll
            for (int e = 0; e < 16; e++) {
                float p = __expf(sarr[e] - mnew);
                rsum += p;
                pb[e] = f2tf32(p);
            }
            rsum += __shfl_xor_sync(0xffffffffu, rsum, 1);
            rsum += __shfl_xor_sync(0xffffffffu, rsum, 2);
            if (t == 0) {
                const float al = __expf(mold - mnew);
                sM[row] = mnew;
                sA[row] = al;
                sL[row] = sL[row] * al + rsum;
            }
            uint4* pd = (uint4*)&sP[row * 68 + t * 16];
            pd[0] = make_uint4(pb[0], pb[1], pb[2], pb[3]);
            pd[1] = make_uint4(pb[4], pb[5], pb[6], pb[7]);
            pd[2] = make_uint4(pb[8], pb[9], pb[10], pb[11]);
            pd[3] = make_uint4(pb[12], pb[13], pb[14], pb[15]);
        }
        __syncthreads();

        // ---- rescale + P@V via mma ----
        {
            const float al0 = sA[16 * rb + g];
            const float al1 = sA[16 * rb + g + 8];
#pragma unroll
            for (int cb = 0; cb < 4; cb++) {
                acc[cb][0] *= al0; acc[cb][1] *= al0;
                acc[cb][2] *= al1; acc[cb][3] *= al1;
            }
            const int prow0 = (16 * rb + g) * 68;
            const int prow1 = (16 * rb + g + 8) * 68;
#pragma unroll
            for (int ks = 0; ks < 8; ks++) {
                const int kc = ks * 8 + t;
                uint32_t a[4] = { sP[prow0 + kc], sP[prow1 + kc],
                                  sP[prow0 + kc + 4], sP[prow1 + kc + 4] };
#pragma unroll
                for (int cb = 0; cb < 4; cb++) {
                    const int col = 8 * (ch * 4 + cb) + g;
                    uint32_t b[2] = { sV[(ks * 8 + t) * 68 + col],
                                      sV[(ks * 8 + t + 4) * 68 + col] };
                    mma_tf32(acc[cb], a, b);
                }
            }
        }
    }

    // ---- finalize ----
    const float linv0 = 1.f / sL[16 * rb + g];
    const float linv1 = 1.f / sL[16 * rb + g + 8];
    const int r0 = i0 + 16 * rb + g;
#pragma unroll
    for (int cb = 0; cb < 4; cb++) {
        const int col = hbase + 8 * (ch * 4 + cb) + 2 * t;
        float2 o0, o1;
        o0.x = acc[cb][0] * linv0; o0.y = acc[cb][1] * linv0;
        o1.x = acc[cb][2] * linv1; o1.y = acc[cb][3] * linv1;
        *(float2*)&av[((size_t)(r0 * BSZ + bi)) * DIM + col] = o0;
        *(float2*)&av[((size_t)((r0 + 8) * BSZ + bi)) * DIM + col] = o1;
    }
}

// ---------------- residual + layernorm (row per block) ----------------
__global__ __launch_bounds__(256) void ln_kernel(
    const float* __restrict__ x, const float* __restrict__ res,
    const float* __restrict__ g, const float* __restrict__ b,
    float* __restrict__ out1, float* __restrict__ out2)
{
    const int row = blockIdx.x;
    const int tid = threadIdx.x;
    float4 xv = *(const float4*)(x + (size_t)row * DIM + tid * 4);
    float4 rv = *(const float4*)(res + (size_t)row * DIM + tid * 4);
    float v0 = xv.x + rv.x, v1 = xv.y + rv.y, v2 = xv.z + rv.z, v3 = xv.w + rv.w;
    float s = v0 + v1 + v2 + v3;
    float q = v0 * v0 + v1 * v1 + v2 * v2 + v3 * v3;
#pragma unroll
    for (int off = 16; off > 0; off >>= 1) {
        s += __shfl_xor_sync(0xffffffffu, s, off);
        q += __shfl_xor_sync(0xffffffffu, q, off);
    }
    __shared__ float sb[8], qb[8];
    const int w = tid >> 5, lane = tid & 31;
    if (lane == 0) { sb[w] = s; qb[w] = q; }
    __syncthreads();
    if (w == 0) {
        float s2 = (lane < 8) ? sb[lane] : 0.f;
        float q2 = (lane < 8) ? qb[lane] : 0.f;
#pragma unroll
        for (int off = 4; off > 0; off >>= 1) {
            s2 += __shfl_xor_sync(0xffffffffu, s2, off);
            q2 += __shfl_xor_sync(0xffffffffu, q2, off);
        }
        if (lane == 0) { sb[0] = s2; qb[0] = q2; }
    }
    __syncthreads();
    const float mean = sb[0] * (1.0f / DIM);
    const float var  = qb[0] * (1.0f / DIM) - mean * mean;
    const float rstd = rsqrtf(var + 1e-5f);
    float4 gv = *(const float4*)(g + tid * 4);
    float4 bv = *(const float4*)(b + tid * 4);
    float4 o;
    o.x = (v0 - mean) * rstd * gv.x + bv.x;
    o.y = (v1 - mean) * rstd * gv.y + bv.y;
    o.z = (v2 - mean) * rstd * gv.z + bv.z;
    o.w = (v3 - mean) * rstd * gv.w + bv.w;
    *(float4*)(out1 + (size_t)row * DIM + tid * 4) = o;
    if (out2) *(float4*)(out2 + (size_t)row * DIM + tid * 4) = o;
}

// ---------------- host orchestration ----------------
extern "C" void kernel_launch(void* const* d_in, const int* in_sizes, int n_in,
                              void* d_out, int out_size) {
    const float* mems = (const float*)d_in[0];
    const float* raw  = (const float*)d_in[1];
    /* d_in[2] = attention_mask: analytic, ignored */
    const float* rwb  = (const float*)d_in[3];
    const float* rrb  = (const float*)d_in[4];
    const float* qkvw = (const float*)d_in[5];
    const float* rw   = (const float*)d_in[6];
    const float* ow   = (const float*)d_in[7];
    const float* ln1g = (const float*)d_in[8];
    const float* ln1b = (const float*)d_in[9];
    const float* fw1  = (const float*)d_in[10];
    const float* fb1  = (const float*)d_in[11];
    const float* fw2  = (const float*)d_in[12];
    const float* fb2  = (const float*)d_in[13];
    const float* ln2g = (const float*)d_in[14];
    const float* ln2b = (const float*)d_in[15];
    float* out = (float*)d_out;

    const bool full_out = out_size >= (NLAY + 2) * NE;   // core + new_mems(5 slabs)
    float* out_mems = full_out ? out + NE : nullptr;

    float *wh, *pos, *rh, *av, *tmp, *core, *core2, *ff;
    cudaGetSymbolAddress((void**)&wh,   g_wheads);
    cudaGetSymbolAddress((void**)&pos,  g_pos);
    cudaGetSymbolAddress((void**)&rh,   g_rhead);
    cudaGetSymbolAddress((void**)&av,   g_attnvec);
    cudaGetSymbolAddress((void**)&tmp,  g_tmp);
    cudaGetSymbolAddress((void**)&core, g_core);
    cudaGetSymbolAddress((void**)&core2,g_core2);
    cudaGetSymbolAddress((void**)&ff,   g_ff);

    cudaFuncSetAttribute((const void*)attn_mma_kernel,
                         cudaFuncAttributeMaxDynamicSharedMemorySize, ATTN2_SMEM_BYTES);

    const int C4 = NE / 4;               // float4 count per slab
    const int CB = (C4 + 255) / 256;

    copy_kernel<<<CB, 256>>>(core, raw, C4);
    if (out_mems) copy_kernel<<<CB, 256>>>(out_mems, raw, C4);
    pos_kernel<<<(KLEN * DIM + 255) / 256, 256>>>(pos);

    for (int i = 0; i < NLAY; i++) {
        // QKV split, reading sources directly (no cat buffer):
        //  - mem rows (from mems[i]) need only K,V (cols 1024..3071)
        //  - q rows (from core) need all 3072 cols
        mma_gemm<<<dim3(16, 16), 256>>>(
            mems + (size_t)i * NE, qkvw + (size_t)i * DIM * 3 * DIM + 1024, wh + 1024,
            2048, 2048, 1024, 1024, 3072, 3072, nullptr, 0);
        mma_gemm<<<dim3(24, 16), 256>>>(
            core, qkvw + (size_t)i * DIM * 3 * DIM,
            wh + (size_t)2048 * 3072,
            2048, 3072, 1024, 1024, 3072, 3072, nullptr, 0);
        mma_gemm<<<dim3(8, 16), 256>>>(
            pos, rw + (size_t)i * DIM * DIM, rh,
            2048, 1024, 1024, 1024, 1024, 1024, nullptr, 0);

        attn_mma_kernel<<<dim3(16, 32), 256, ATTN2_SMEM_BYTES>>>(wh, rh, rwb, rrb, av);

        mma_gemm<<<dim3(8, 16), 256>>>(
            av, ow + (size_t)i * DIM * DIM, tmp,
            2048, 1024, 1024, 1024, 1024, 1024, nullptr, 0);
        ln_kernel<<<2048, 256>>>(tmp, core, ln1g + i * DIM, ln1b + i * DIM, core2, nullptr);

        mma_gemm<<<dim3(8, 16), 256>>>(
            core2, fw1 + (size_t)i * DIM * DIM, ff,
            2048, 1024, 1024, 1024, 1024, 1024, fb1 + i * DIM, 1);
        mma_gemm<<<dim3(8, 16), 256>>>(
            ff, fw2 + (size_t)i * DIM * DIM, tmp,
            2048, 1024, 1024, 1024, 1024, 1024, fb2 + i * DIM, 0);
        float* lnDst = (i == NLAY - 1) ? out : core;
        ln_kernel<<<2048, 256>>>(tmp, core2, ln2g + i * DIM, ln2b + i * DIM, lnDst,
                                 out_mems ? out_mems + (size_t)(i + 1) * NE : nullptr);
    }
}

// round 12
// speedup vs baseline: 1.2252x; 1.2252x over previous
#include <cuda_runtime.h>
#include <cuda_fp16.h>
#include <math.h>
#include <stdint.h>

#define L_Q   1024
#define BSZ   2
#define DIM   1024
#define NHEAD 16
#define DHEAD 64
#define NLAY  4
#define MLEN  1024
#define KLEN  2048
#define NE    (L_Q*BSZ*DIM)   /* 2097152 floats per (L,B,D) slab */

// ---------------- scratch (device globals; no allocation allowed) ----------------
__device__ float g_wheads[(size_t)KLEN*BSZ*3*DIM];   // 50 MB
__device__ float g_pos[(size_t)KLEN*DIM];            // 8 MB
__device__ float g_rhead[(size_t)KLEN*DIM];          // 8 MB
__device__ float g_attnvec[NE];
__device__ float g_tmp[NE];
__device__ float g_core[NE];
__device__ float g_core2[NE];
__device__ float g_ff[NE];

// ---------------- simple float4 copy ----------------
__global__ void copy_kernel(float* __restrict__ dst, const float* __restrict__ src, int n4) {
    int i = blockIdx.x * blockDim.x + threadIdx.x;
    if (i < n4) ((float4*)dst)[i] = ((const float4*)src)[i];
}

// ---------------- positional embedding ----------------
__global__ void pos_kernel(float* __restrict__ pos) {
    int idx = blockIdx.x * blockDim.x + threadIdx.x;
    if (idx >= KLEN * DIM) return;
    int j = idx >> 10;           // 0..2047
    int i = idx & 1023;          // 0..1023
    int t = i & 511;
    float x = (float)(2 * t) * (1.0f / 1024.0f);
    float invf = expf(-x * 9.210340371976184f);   // 10000^{-x}
    float arg = (float)(KLEN - 1 - j) * invf;
    pos[idx] = (i < 512) ? sinf(arg) : cosf(arg);
}

// ---------------- helpers ----------------
__device__ __forceinline__ uint32_t f2tf32(float f) {
    uint32_t u;
    asm("cvt.rna.tf32.f32 %0, %1;" : "=r"(u) : "f"(f));
    return u;
}
__device__ __forceinline__ uint4 cvt4(float4 v) {
    return make_uint4(f2tf32(v.x), f2tf32(v.y), f2tf32(v.z), f2tf32(v.w));
}
__device__ __forceinline__ void mma_tf32(float* c, const uint32_t* a, const uint32_t* b) {
    asm volatile(
        "mma.sync.aligned.m16n8k8.row.col.f32.tf32.tf32.f32 "
        "{%0,%1,%2,%3}, {%4,%5,%6,%7}, {%8,%9}, {%0,%1,%2,%3};"
        : "+f"(c[0]), "+f"(c[1]), "+f"(c[2]), "+f"(c[3])
        : "r"(a[0]), "r"(a[1]), "r"(a[2]), "r"(a[3]), "r"(b[0]), "r"(b[1]));
}
// pack (lo,hi) floats -> half2 bits (lo in low half)
__device__ __forceinline__ uint32_t pack_h2(float lo, float hi) {
    uint32_t r;
    asm("cvt.rn.f16x2.f32 %0, %1, %2;" : "=r"(r) : "f"(hi), "f"(lo));
    return r;
}
__device__ __forceinline__ void mma_f16(float* c, const uint32_t* a, const uint32_t* b) {
    asm volatile(
        "mma.sync.aligned.m16n8k16.row.col.f32.f16.f16.f32 "
        "{%0,%1,%2,%3}, {%4,%5,%6,%7}, {%8,%9}, {%0,%1,%2,%3};"
        : "+f"(c[0]), "+f"(c[1]), "+f"(c[2]), "+f"(c[3])
        : "r"(a[0]), "r"(a[1]), "r"(a[2]), "r"(a[3]), "r"(b[0]), "r"(b[1]));
}

// ---------------- fp16 tensor-core GEMM: 128x128 block, K-tile 32, 2-stage ----
// A[M,K] lda, B[K,N] ldb, C[M,N] ldc (row-major fp32). fp16 operands, fp32 accum.
// Fragment-major smem layout (half2 units).
__global__ __launch_bounds__(256) void mma_gemm(
    const float* __restrict__ A, const float* __restrict__ B, float* __restrict__ C,
    int M, int N, int K, int lda, int ldb, int ldc,
    const float* __restrict__ bias, int relu)
{
    __shared__ __align__(16) uint32_t As[2][2048];
    __shared__ __align__(16) uint32_t Bs[2][2048];

    const int tid = threadIdx.x;
    const int lane = tid & 31;
    const int w = tid >> 5;
    const int wr = w & 1;            // 0..1 (m 64-half)
    const int wc = w >> 1;           // 0..3 (n 32-quarter)
    const int bx = blockIdx.x, by = blockIdx.y;

    // ---- A staging: thread = (row ar, k-half kh); 8 half2 STS, rotated ----
    const int ar  = tid >> 1;              // 0..127
    const int kh  = tid & 1;               // k 0..15 or 16..31
    const int ac  = ((ar >> 1) & 3) + 4 * kh;   // rotation class
    const int abase = (((kh * 8 + (ar >> 4)) * 32 + (ar & 7) * 4) << 2) + ((ar >> 3) & 1);
    const float* Ag = A + (size_t)(by * 128 + ar) * lda + kh * 16;

    // ---- B staging: warp w -> nb pair {2w, 2w+1}; lane l -> (nn=l>>2, ppl=l&3) ----
    const int bl   = lane;
    const int bnn  = bl >> 2;
    const int bppl = bl & 3;
    const int blh  = (bl >> 4) & 1;        // rotation for q
    const int nb0  = (tid >> 5) << 1;
    const int bcol0 = bx * 128;

    float acc[4][4][4];
#pragma unroll
    for (int mi = 0; mi < 4; mi++)
#pragma unroll
        for (int ni = 0; ni < 4; ni++)
#pragma unroll
            for (int q = 0; q < 4; q++) acc[mi][ni][q] = 0.f;

    float4 pa[4];
    float pbF[16];

    // prefetch tile 0
#pragma unroll
    for (int tt = 0; tt < 4; tt++) pa[tt] = *(const float4*)(Ag + tt * 4);
#pragma unroll
    for (int j = 0; j < 4; j++) {
        const int ppq4 = (j + blh) & 3;
        const int p = ppq4 * 4 + bppl;
#pragma unroll
        for (int nbi = 0; nbi < 2; nbi++) {
            const int n = (nb0 + nbi) * 8 + bnn;
            pbF[j * 4 + nbi * 2 + 0] = B[(size_t)(2 * p) * ldb + bcol0 + n];
            pbF[j * 4 + nbi * 2 + 1] = B[(size_t)(2 * p + 1) * ldb + bcol0 + n];
        }
    }
    // stage tile 0 -> buf 0
#pragma unroll
    for (int j = 0; j < 8; j++) {
        const int pp2 = (j + ac) & 7;
        const int fl = pp2 * 2;
        const float* f = (const float*)&pa[fl >> 2];
        As[0][abase + ((pp2 & 3) << 2) + ((pp2 >> 2) << 1)] = pack_h2(f[fl & 3], f[(fl & 3) + 1]);
    }
#pragma unroll
    for (int j = 0; j < 4; j++) {
        const int ppq4 = (j + blh) & 3;
        const int ks = ppq4 >> 1, q = ppq4 & 1;
#pragma unroll
        for (int nbi = 0; nbi < 2; nbi++) {
            const int nb = nb0 + nbi;
            Bs[0][(((ks * 16 + nb) * 32 + bl) << 1) + q] =
                pack_h2(pbF[j * 4 + nbi * 2], pbF[j * 4 + nbi * 2 + 1]);
        }
    }
    __syncthreads();

    const int NT = K >> 5;
    for (int T = 0; T < NT; T++) {
        const int buf = T & 1;
        if (T + 1 < NT) {
            const int off = (T + 1) << 5;
#pragma unroll
            for (int tt = 0; tt < 4; tt++) pa[tt] = *(const float4*)(Ag + off + tt * 4);
#pragma unroll
            for (int j = 0; j < 4; j++) {
                const int ppq4 = (j + blh) & 3;
                const int p = ppq4 * 4 + bppl;
#pragma unroll
                for (int nbi = 0; nbi < 2; nbi++) {
                    const int n = (nb0 + nbi) * 8 + bnn;
                    pbF[j * 4 + nbi * 2 + 0] = B[(size_t)(off + 2 * p) * ldb + bcol0 + n];
                    pbF[j * 4 + nbi * 2 + 1] = B[(size_t)(off + 2 * p + 1) * ldb + bcol0 + n];
                }
            }
        }
        // compute: 2 k16 steps, 16 mma each
#pragma unroll
        for (int ks = 0; ks < 2; ks++) {
            uint32_t afr[4][4], bfr[4][2];
#pragma unroll
            for (int mi = 0; mi < 4; mi++) {
                const uint4 v = *(const uint4*)&As[buf][(((ks * 8 + wr * 4 + mi) * 32 + lane) << 2)];
                afr[mi][0] = v.x; afr[mi][1] = v.y; afr[mi][2] = v.z; afr[mi][3] = v.w;
            }
#pragma unroll
            for (int ni = 0; ni < 4; ni++) {
                const uint2 v = *(const uint2*)&Bs[buf][(((ks * 16 + wc * 4 + ni) * 32 + lane) << 1)];
                bfr[ni][0] = v.x; bfr[ni][1] = v.y;
            }
#pragma unroll
            for (int mi = 0; mi < 4; mi++)
#pragma unroll
                for (int ni = 0; ni < 4; ni++)
                    mma_f16(acc[mi][ni], afr[mi], bfr[ni]);
        }
        // stage next tile -> other buffer
        if (T + 1 < NT) {
            const int nb2 = buf ^ 1;
#pragma unroll
            for (int j = 0; j < 8; j++) {
                const int pp2 = (j + ac) & 7;
                const int fl = pp2 * 2;
                const float* f = (const float*)&pa[fl >> 2];
                As[nb2][abase + ((pp2 & 3) << 2) + ((pp2 >> 2) << 1)] =
                    pack_h2(f[fl & 3], f[(fl & 3) + 1]);
            }
#pragma unroll
            for (int j = 0; j < 4; j++) {
                const int ppq4 = (j + blh) & 3;
                const int ks = ppq4 >> 1, q = ppq4 & 1;
#pragma unroll
                for (int nbi = 0; nbi < 2; nbi++) {
                    const int nb = nb0 + nbi;
                    Bs[nb2][(((ks * 16 + nb) * 32 + bl) << 1) + q] =
                        pack_h2(pbF[j * 4 + nbi * 2], pbF[j * 4 + nbi * 2 + 1]);
                }
            }
        }
        __syncthreads();
    }

    const int g = lane >> 2;
    const int t = lane & 3;
#pragma unroll
    for (int mi = 0; mi < 4; mi++) {
        const int r0 = by * 128 + wr * 64 + mi * 16 + g;
#pragma unroll
        for (int ni = 0; ni < 4; ni++) {
            const int c0 = bx * 128 + wc * 32 + ni * 8 + t * 2;
            float b0 = 0.f, b1 = 0.f;
            if (bias) { b0 = bias[c0]; b1 = bias[c0 + 1]; }
            float2 o0, o1;
            o0.x = acc[mi][ni][0] + b0; o0.y = acc[mi][ni][1] + b1;
            o1.x = acc[mi][ni][2] + b0; o1.y = acc[mi][ni][3] + b1;
            if (relu) {
                o0.x = fmaxf(o0.x, 0.f); o0.y = fmaxf(o0.y, 0.f);
                o1.x = fmaxf(o1.x, 0.f); o1.y = fmaxf(o1.y, 0.f);
            }
            *(float2*)&C[(size_t)r0 * ldc + c0] = o0;
            *(float2*)&C[(size_t)(r0 + 8) * ldc + c0] = o1;
        }
    }
}

// ---------------- tensor-core fused rel-attention (pitch-68 + E-band skip) ----
#define AT_QW 0                     /* 64x68 tf32 */
#define AT_QR 4352
#define AT_K  8704
#define AT_R  13056                 /* 128x68 (127 used) */
#define AT_V  21760
#define AT_S  26112                 /* 64x68 f32 */
#define AT_E  30464                 /* 64x136 f32 */
#define AT_P  39168                 /* 64x68 tf32 */
#define AT_M  43520
#define AT_L  43584
#define AT_A  43648
#define ATTN2_SMEM_FLOATS 43712
#define ATTN2_SMEM_BYTES  (ATTN2_SMEM_FLOATS * 4)

__global__ __launch_bounds__(256) void attn_mma_kernel(
    const float* __restrict__ wh, const float* __restrict__ rh,
    const float* __restrict__ rwb, const float* __restrict__ rrb,
    float* __restrict__ av)
{
    extern __shared__ float smf[];
    uint32_t* sQw = (uint32_t*)(smf + AT_QW);
    uint32_t* sQr = (uint32_t*)(smf + AT_QR);
    uint32_t* sK  = (uint32_t*)(smf + AT_K);
    uint32_t* sR  = (uint32_t*)(smf + AT_R);
    uint32_t* sV  = (uint32_t*)(smf + AT_V);
    float*    sS  = smf + AT_S;
    float*    sE  = smf + AT_E;
    uint32_t* sP  = (uint32_t*)(smf + AT_P);
    float*    sM  = smf + AT_M;
    float*    sL  = smf + AT_L;
    float*    sA  = smf + AT_A;

    const int i0 = (15 - blockIdx.x) << 6;   // heaviest q-tile first
    const int bi = blockIdx.y >> 4;
    const int hn = blockIdx.y & 15;
    const int tid = threadIdx.x;
    const int lane = tid & 31;
    const int w = tid >> 5;
    const int rb = w >> 1;           // 0..3
    const int ch = w & 1;            // 0..1
    const int g = lane >> 2;         // 0..7
    const int t = lane & 3;          // 0..3
    const int hbase = hn << 6;

    // E diagonal-band block bounds for this warp (rows 16rb..16rb+15, col half ch)
    int ebmin = 41 - 16 * rb - 64 * ch;
    ebmin = ebmin <= 0 ? 0 : ((ebmin + 7) >> 3);
    int ebmax = (126 - 16 * rb - 64 * ch) >> 3;
    if (ebmax > 7) ebmax = 7;

    // staging lane coords (float4 granularity)
    const int svr = tid >> 4;             // row 0..15 base (of 64, via +u*16)
    const int svc = (tid & 15) << 2;      // col 0,4,..,60

    // ---- load Q tiles (bias folded), vectorized ----
    {
        float4 w4 = *(const float4*)&rwb[hbase + svc];
        float4 r4 = *(const float4*)&rrb[hbase + svc];
#pragma unroll
        for (int u = 0; u < 4; u++) {
            const int r = svr + u * 16;
            const size_t base = ((size_t)((MLEN + i0 + r) * BSZ + bi)) * 3072 + hbase + svc;
            float4 q4 = *(const float4*)&wh[base];
            float4 aw = make_float4(q4.x + w4.x, q4.y + w4.y, q4.z + w4.z, q4.w + w4.w);
            float4 ar = make_float4(q4.x + r4.x, q4.y + r4.y, q4.z + r4.z, q4.w + r4.w);
            *(uint4*)&sQw[r * 68 + svc] = cvt4(aw);
            *(uint4*)&sQr[r * 68 + svc] = cvt4(ar);
        }
    }
    if (tid < 64) { sM[tid] = -3e38f; sL[tid] = 0.f; }

    float acc[4][4];   // PV accum frags
#pragma unroll
    for (int cb = 0; cb < 4; cb++)
#pragma unroll
        for (int q = 0; q < 4; q++) acc[cb][q] = 0.f;

    const int arow0 = (16 * rb + g) * 68;
    const int arow1 = (16 * rb + g + 8) * 68;
    const int nkt = 17 + (i0 >> 6);

    // K/V prefetch registers for tile 0
    float4 pk[4], pv[4];
#pragma unroll
    for (int u = 0; u < 4; u++) {
        const int r = svr + u * 16;
        const size_t base = ((size_t)(r * BSZ + bi)) * 3072 + hbase + svc;
        pk[u] = *(const float4*)&wh[base + 1024];
        pv[u] = *(const float4*)&wh[base + 2048];
    }

    for (int kt = 0; kt < nkt; kt++) {
        const int j0 = kt << 6;
        __syncthreads();
        // ---- store prefetched K/V; stage R directly ----
#pragma unroll
        for (int u = 0; u < 4; u++) {
            const int r = svr + u * 16;
            *(uint4*)&sK[r * 68 + svc] = cvt4(pk[u]);
            *(uint4*)&sV[r * 68 + svc] = cvt4(pv[u]);
        }
        const int rbase = j0 + MLEN - 1 - i0 - 63;
#pragma unroll
        for (int u = 0; u < 8; u++) {
            const int idx = tid + u * 256;
            if (idx < 2032) {
                const int r = idx >> 4, c4 = (idx & 15) << 2;
                int rg = rbase + r;
                rg = rg < 0 ? 0 : (rg > KLEN - 1 ? KLEN - 1 : rg);
                const float4 v = *(const float4*)&rh[(size_t)rg * DIM + hbase + c4];
                *(uint4*)&sR[r * 68 + c4] = cvt4(v);
            }
        }
        __syncthreads();

        // ---- prefetch next tile's K/V (overlaps mma below) ----
        if (kt + 1 < nkt) {
#pragma unroll
            for (int u = 0; u < 4; u++) {
                const int r = svr + u * 16;
                const size_t base = ((size_t)(((j0 + 64) + r) * BSZ + bi)) * 3072 + hbase + svc;
                pk[u] = *(const float4*)&wh[base + 1024];
                pv[u] = *(const float4*)&wh[base + 2048];
            }
        }

        // ---- S and E via mma (E restricted to diagonal band blocks) ----
        float Sacc[4][4], Eacc[8][4];
#pragma unroll
        for (int cb = 0; cb < 4; cb++)
#pragma unroll
            for (int q = 0; q < 4; q++) Sacc[cb][q] = 0.f;
#pragma unroll
        for (int eb = 0; eb < 8; eb++)
#pragma unroll
            for (int q = 0; q < 4; q++) Eacc[eb][q] = 0.f;

#pragma unroll
        for (int ks = 0; ks < 8; ks++) {
            const int kc = ks * 8 + t;
            uint32_t aw[4], ar[4];
            aw[0] = sQw[arow0 + kc]; aw[1] = sQw[arow1 + kc];
            aw[2] = sQw[arow0 + kc + 4]; aw[3] = sQw[arow1 + kc + 4];
            ar[0] = sQr[arow0 + kc]; ar[1] = sQr[arow1 + kc];
            ar[2] = sQr[arow0 + kc + 4]; ar[3] = sQr[arow1 + kc + 4];
#pragma unroll
            for (int cb = 0; cb < 4; cb++) {
                const int kr = (8 * (ch * 4 + cb) + g) * 68 + kc;
                uint32_t b[2] = { sK[kr], sK[kr + 4] };
                mma_tf32(Sacc[cb], aw, b);
            }
#pragma unroll
            for (int eb = 0; eb < 8; eb++) {
                if (eb >= ebmin && eb <= ebmax) {
                    const int rr = (8 * (ch * 8 + eb) + g) * 68 + kc;
                    uint32_t b[2] = { sR[rr], sR[rr + 4] };
                    mma_tf32(Eacc[eb], ar, b);
                }
            }
        }
        // write S, E to smem (float2 stores)
#pragma unroll
        for (int cb = 0; cb < 4; cb++) {
            const int col = 8 * (ch * 4 + cb) + 2 * t;
            *(float2*)&sS[(16 * rb + g) * 68 + col]     = make_float2(Sacc[cb][0], Sacc[cb][1]);
            *(float2*)&sS[(16 * rb + g + 8) * 68 + col] = make_float2(Sacc[cb][2], Sacc[cb][3]);
        }
#pragma unroll
        for (int eb = 0; eb < 8; eb++) {
            if (eb >= ebmin && eb <= ebmax) {
                const int col = 8 * (ch * 8 + eb) + 2 * t;
                *(float2*)&sE[(16 * rb + g) * 136 + col]     = make_float2(Eacc[eb][0], Eacc[eb][1]);
                *(float2*)&sE[(16 * rb + g + 8) * 136 + col] = make_float2(Eacc[eb][2], Eacc[eb][3]);
            }
        }
        __syncthreads();

        // ---- online softmax: warp w owns rows w*8..w*8+7; lane quad per row ----
        {
            const int row = w * 8 + g;
            const int qi = i0 + row;
            float sarr[16];
            {
                const float4* srow = (const float4*)&sS[row * 68 + t * 16];
#pragma unroll
                for (int v4 = 0; v4 < 4; v4++) {
                    float4 s4 = srow[v4];
                    sarr[v4 * 4 + 0] = s4.x; sarr[v4 * 4 + 1] = s4.y;
                    sarr[v4 * 4 + 2] = s4.z; sarr[v4 * 4 + 3] = s4.w;
                }
            }
            const int ebase = row * 135 + t * 16 + 63;   // row*136 + (t*16 - row + 63)
            float tmax = -3e38f;
#pragma unroll
            for (int e = 0; e < 16; e++) {
                float vv = (sarr[e] + sE[ebase + e]) * 0.125f;
                if (j0 + t * 16 + e > MLEN + qi) vv = -3e38f;
                sarr[e] = vv;
                tmax = fmaxf(tmax, vv);
            }
            tmax = fmaxf(tmax, __shfl_xor_sync(0xffffffffu, tmax, 1));
            tmax = fmaxf(tmax, __shfl_xor_sync(0xffffffffu, tmax, 2));
            const float mold = sM[row];
            const float mnew = fmaxf(mold, tmax);
            float rsum = 0.f;
            uint32_t pb[16];
#pragma unroll
            for (int e = 0; e < 16; e++) {
                float p = __expf(sarr[e] - mnew);
                rsum += p;
                pb[e] = f2tf32(p);
            }
            rsum += __shfl_xor_sync(0xffffffffu, rsum, 1);
            rsum += __shfl_xor_sync(0xffffffffu, rsum, 2);
            if (t == 0) {
                const float al = __expf(mold - mnew);
                sM[row] = mnew;
                sA[row] = al;
                sL[row] = sL[row] * al + rsum;
            }
            uint4* pd = (uint4*)&sP[row * 68 + t * 16];
            pd[0] = make_uint4(pb[0], pb[1], pb[2], pb[3]);
            pd[1] = make_uint4(pb[4], pb[5], pb[6], pb[7]);
            pd[2] = make_uint4(pb[8], pb[9], pb[10], pb[11]);
            pd[3] = make_uint4(pb[12], pb[13], pb[14], pb[15]);
        }
        __syncthreads();

        // ---- rescale + P@V via mma ----
        {
            const float al0 = sA[16 * rb + g];
            const float al1 = sA[16 * rb + g + 8];
#pragma unroll
            for (int cb = 0; cb < 4; cb++) {
                acc[cb][0] *= al0; acc[cb][1] *= al0;
                acc[cb][2] *= al1; acc[cb][3] *= al1;
            }
            const int prow0 = (16 * rb + g) * 68;
            const int prow1 = (16 * rb + g + 8) * 68;
#pragma unroll
            for (int ks = 0; ks < 8; ks++) {
                const int kc = ks * 8 + t;
                uint32_t a[4] = { sP[prow0 + kc], sP[prow1 + kc],
                                  sP[prow0 + kc + 4], sP[prow1 + kc + 4] };
#pragma unroll
                for (int cb = 0; cb < 4; cb++) {
                    const int col = 8 * (ch * 4 + cb) + g;
                    uint32_t b[2] = { sV[(ks * 8 + t) * 68 + col],
                                      sV[(ks * 8 + t + 4) * 68 + col] };
                    mma_tf32(acc[cb], a, b);
                }
            }
        }
    }

    // ---- finalize ----
    const float linv0 = 1.f / sL[16 * rb + g];
    const float linv1 = 1.f / sL[16 * rb + g + 8];
    const int r0 = i0 + 16 * rb + g;
#pragma unroll
    for (int cb = 0; cb < 4; cb++) {
        const int col = hbase + 8 * (ch * 4 + cb) + 2 * t;
        float2 o0, o1;
        o0.x = acc[cb][0] * linv0; o0.y = acc[cb][1] * linv0;
        o1.x = acc[cb][2] * linv1; o1.y = acc[cb][3] * linv1;
        *(float2*)&av[((size_t)(r0 * BSZ + bi)) * DIM + col] = o0;
        *(float2*)&av[((size_t)((r0 + 8) * BSZ + bi)) * DIM + col] = o1;
    }
}

// ---------------- residual + layernorm (row per block) ----------------
__global__ __launch_bounds__(256) void ln_kernel(
    const float* __restrict__ x, const float* __restrict__ res,
    const float* __restrict__ g, const float* __restrict__ b,
    float* __restrict__ out1, float* __restrict__ out2)
{
    const int row = blockIdx.x;
    const int tid = threadIdx.x;
    float4 xv = *(const float4*)(x + (size_t)row * DIM + tid * 4);
    float4 rv = *(const float4*)(res + (size_t)row * DIM + tid * 4);
    float v0 = xv.x + rv.x, v1 = xv.y + rv.y, v2 = xv.z + rv.z, v3 = xv.w + rv.w;
    float s = v0 + v1 + v2 + v3;
    float q = v0 * v0 + v1 * v1 + v2 * v2 + v3 * v3;
#pragma unroll
    for (int off = 16; off > 0; off >>= 1) {
        s += __shfl_xor_sync(0xffffffffu, s, off);
        q += __shfl_xor_sync(0xffffffffu, q, off);
    }
    __shared__ float sb[8], qb[8];
    const int w = tid >> 5, lane = tid & 31;
    if (lane == 0) { sb[w] = s; qb[w] = q; }
    __syncthreads();
    if (w == 0) {
        float s2 = (lane < 8) ? sb[lane] : 0.f;
        float q2 = (lane < 8) ? qb[lane] : 0.f;
#pragma unroll
        for (int off = 4; off > 0; off >>= 1) {
            s2 += __shfl_xor_sync(0xffffffffu, s2, off);
            q2 += __shfl_xor_sync(0xffffffffu, q2, off);
        }
        if (lane == 0) { sb[0] = s2; qb[0] = q2; }
    }
    __syncthreads();
    const float mean = sb[0] * (1.0f / DIM);
    const float var  = qb[0] * (1.0f / DIM) - mean * mean;
    const float rstd = rsqrtf(var + 1e-5f);
    float4 gv = *(const float4*)(g + tid * 4);
    float4 bv = *(const float4*)(b + tid * 4);
    float4 o;
    o.x = (v0 - mean) * rstd * gv.x + bv.x;
    o.y = (v1 - mean) * rstd * gv.y + bv.y;
    o.z = (v2 - mean) * rstd * gv.z + bv.z;
    o.w = (v3 - mean) * rstd * gv.w + bv.w;
    *(float4*)(out1 + (size_t)row * DIM + tid * 4) = o;
    if (out2) *(float4*)(out2 + (size_t)row * DIM + tid * 4) = o;
}

// ---------------- host orchestration ----------------
extern "C" void kernel_launch(void* const* d_in, const int* in_sizes, int n_in,
                              void* d_out, int out_size) {
    const float* mems = (const float*)d_in[0];
    const float* raw  = (const float*)d_in[1];
    /* d_in[2] = attention_mask: analytic, ignored */
    const float* rwb  = (const float*)d_in[3];
    const float* rrb  = (const float*)d_in[4];
    const float* qkvw = (const float*)d_in[5];
    const float* rw   = (const float*)d_in[6];
    const float* ow   = (const float*)d_in[7];
    const float* ln1g = (const float*)d_in[8];
    const float* ln1b = (const float*)d_in[9];
    const float* fw1  = (const float*)d_in[10];
    const float* fb1  = (const float*)d_in[11];
    const float* fw2  = (const float*)d_in[12];
    const float* fb2  = (const float*)d_in[13];
    const float* ln2g = (const float*)d_in[14];
    const float* ln2b = (const float*)d_in[15];
    float* out = (float*)d_out;

    const bool full_out = out_size >= (NLAY + 2) * NE;   // core + new_mems(5 slabs)
    float* out_mems = full_out ? out + NE : nullptr;

    float *wh, *pos, *rh, *av, *tmp, *core, *core2, *ff;
    cudaGetSymbolAddress((void**)&wh,   g_wheads);
    cudaGetSymbolAddress((void**)&pos,  g_pos);
    cudaGetSymbolAddress((void**)&rh,   g_rhead);
    cudaGetSymbolAddress((void**)&av,   g_attnvec);
    cudaGetSymbolAddress((void**)&tmp,  g_tmp);
    cudaGetSymbolAddress((void**)&core, g_core);
    cudaGetSymbolAddress((void**)&core2,g_core2);
    cudaGetSymbolAddress((void**)&ff,   g_ff);

    cudaFuncSetAttribute((const void*)attn_mma_kernel,
                         cudaFuncAttributeMaxDynamicSharedMemorySize, ATTN2_SMEM_BYTES);

    const int C4 = NE / 4;               // float4 count per slab
    const int CB = (C4 + 255) / 256;

    copy_kernel<<<CB, 256>>>(core, raw, C4);
    if (out_mems) copy_kernel<<<CB, 256>>>(out_mems, raw, C4);
    pos_kernel<<<(KLEN * DIM + 255) / 256, 256>>>(pos);

    for (int i = 0; i < NLAY; i++) {
        // QKV split, reading sources directly (no cat buffer):
        //  - mem rows (from mems[i]) need only K,V (cols 1024..3071)
        //  - q rows (from core) need all 3072 cols
        mma_gemm<<<dim3(16, 16), 256>>>(
            mems + (size_t)i * NE, qkvw + (size_t)i * DIM * 3 * DIM + 1024, wh + 1024,
            2048, 2048, 1024, 1024, 3072, 3072, nullptr, 0);
        mma_gemm<<<dim3(24, 16), 256>>>(
            core, qkvw + (size_t)i * DIM * 3 * DIM,
            wh + (size_t)2048 * 3072,
            2048, 3072, 1024, 1024, 3072, 3072, nullptr, 0);
        mma_gemm<<<dim3(8, 16), 256>>>(
            pos, rw + (size_t)i * DIM * DIM, rh,
            2048, 1024, 1024, 1024, 1024, 1024, nullptr, 0);

        attn_mma_kernel<<<dim3(16, 32), 256, ATTN2_SMEM_BYTES>>>(wh, rh, rwb, rrb, av);

        mma_gemm<<<dim3(8, 16), 256>>>(
            av, ow + (size_t)i * DIM * DIM, tmp,
            2048, 1024, 1024, 1024, 1024, 1024, nullptr, 0);
        ln_kernel<<<2048, 256>>>(tmp, core, ln1g + i * DIM, ln1b + i * DIM, core2, nullptr);

        mma_gemm<<<dim3(8, 16), 256>>>(
            core2, fw1 + (size_t)i * DIM * DIM, ff,
            2048, 1024, 1024, 1024, 1024, 1024, fb1 + i * DIM, 1);
        mma_gemm<<<dim3(8, 16), 256>>>(
            ff, fw2 + (size_t)i * DIM * DIM, tmp,
            2048, 1024, 1024, 1024, 1024, 1024, fb2 + i * DIM, 0);
        float* lnDst = (i == NLAY - 1) ? out : core;
        ln_kernel<<<2048, 256>>>(tmp, core2, ln2g + i * DIM, ln2b + i * DIM, lnDst,
                                 out_mems ? out_mems + (size_t)(i + 1) * NE : nullptr);
    }
}

// round 13
// speedup vs baseline: 1.3039x; 1.0642x over previous
#include <cuda_runtime.h>
#include <cuda_fp16.h>
#include <math.h>
#include <stdint.h>

#define L_Q   1024
#define BSZ   2
#define DIM   1024
#define NHEAD 16
#define DHEAD 64
#define NLAY  4
#define MLEN  1024
#define KLEN  2048
#define NE    (L_Q*BSZ*DIM)   /* 2097152 floats per (L,B,D) slab */

// ---------------- scratch (device globals; no allocation allowed) ----------------
__device__ float g_wheads[(size_t)KLEN*BSZ*3*DIM];   // 50 MB
__device__ float g_pos[(size_t)KLEN*DIM];            // 8 MB
__device__ float g_rhead[(size_t)KLEN*DIM];          // 8 MB
__device__ float g_attnvec[NE];
__device__ float g_tmp[NE];
__device__ float g_core[NE];
__device__ float g_core2[NE];
__device__ float g_ff[NE];

// ---------------- simple float4 copy ----------------
__global__ void copy_kernel(float* __restrict__ dst, const float* __restrict__ src, int n4) {
    int i = blockIdx.x * blockDim.x + threadIdx.x;
    if (i < n4) ((float4*)dst)[i] = ((const float4*)src)[i];
}

// ---------------- positional embedding ----------------
__global__ void pos_kernel(float* __restrict__ pos) {
    int idx = blockIdx.x * blockDim.x + threadIdx.x;
    if (idx >= KLEN * DIM) return;
    int j = idx >> 10;           // 0..2047
    int i = idx & 1023;          // 0..1023
    int t = i & 511;
    float x = (float)(2 * t) * (1.0f / 1024.0f);
    float invf = expf(-x * 9.210340371976184f);   // 10000^{-x}
    float arg = (float)(KLEN - 1 - j) * invf;
    pos[idx] = (i < 512) ? sinf(arg) : cosf(arg);
}

// ---------------- helpers ----------------
__device__ __forceinline__ uint32_t f2tf32(float f) {
    uint32_t u;
    asm("cvt.rna.tf32.f32 %0, %1;" : "=r"(u) : "f"(f));
    return u;
}
__device__ __forceinline__ uint4 cvt4(float4 v) {
    return make_uint4(f2tf32(v.x), f2tf32(v.y), f2tf32(v.z), f2tf32(v.w));
}
__device__ __forceinline__ void mma_tf32(float* c, const uint32_t* a, const uint32_t* b) {
    asm volatile(
        "mma.sync.aligned.m16n8k8.row.col.f32.tf32.tf32.f32 "
        "{%0,%1,%2,%3}, {%4,%5,%6,%7}, {%8,%9}, {%0,%1,%2,%3};"
        : "+f"(c[0]), "+f"(c[1]), "+f"(c[2]), "+f"(c[3])
        : "r"(a[0]), "r"(a[1]), "r"(a[2]), "r"(a[3]), "r"(b[0]), "r"(b[1]));
}
// pack (lo,hi) floats -> half2 bits (lo in low half)
__device__ __forceinline__ uint32_t pack_h2(float lo, float hi) {
    uint32_t r;
    asm("cvt.rn.f16x2.f32 %0, %1, %2;" : "=r"(r) : "f"(hi), "f"(lo));
    return r;
}
__device__ __forceinline__ void mma_f16(float* c, const uint32_t* a, const uint32_t* b) {
    asm volatile(
        "mma.sync.aligned.m16n8k16.row.col.f32.f16.f16.f32 "
        "{%0,%1,%2,%3}, {%4,%5,%6,%7}, {%8,%9}, {%0,%1,%2,%3};"
        : "+f"(c[0]), "+f"(c[1]), "+f"(c[2]), "+f"(c[3])
        : "r"(a[0]), "r"(a[1]), "r"(a[2]), "r"(a[3]), "r"(b[0]), "r"(b[1]));
}

// ---------------- fp16 tensor-core GEMM: 128x128 block, K-tile 32, 2-stage ----
// A[M,K] lda, B[K,N] ldb, C[M,N] ldc (row-major fp32). fp16 operands, fp32 accum.
// Prepacked half2 prefetch registers; 2 CTAs/SM via launch bounds.
__global__ __launch_bounds__(256, 2) void mma_gemm(
    const float* __restrict__ A, const float* __restrict__ B, float* __restrict__ C,
    int M, int N, int K, int lda, int ldb, int ldc,
    const float* __restrict__ bias, int relu)
{
    __shared__ __align__(16) uint32_t As[2][2048];
    __shared__ __align__(16) uint32_t Bs[2][2048];

    const int tid = threadIdx.x;
    const int lane = tid & 31;
    const int w = tid >> 5;
    const int wr = w & 1;            // 0..1 (m 64-half)
    const int wc = w >> 1;           // 0..3 (n 32-quarter)
    const int bx = blockIdx.x, by = blockIdx.y;

    // ---- A staging: thread = (row ar, k-half kh); 8 half2 STS, rotated ----
    const int ar  = tid >> 1;              // 0..127
    const int kh  = tid & 1;               // k 0..15 or 16..31
    const int ac  = ((ar >> 1) & 3) + 4 * kh;   // rotation class
    const int abase = (((kh * 8 + (ar >> 4)) * 32 + (ar & 7) * 4) << 2) + ((ar >> 3) & 1);
    const float* Ag = A + (size_t)(by * 128 + ar) * lda + kh * 16;

    // ---- B staging: warp w -> nb pair {2w, 2w+1}; lane l -> (nn=l>>2, ppl=l&3) ----
    const int bl   = lane;
    const int bnn  = bl >> 2;
    const int bppl = bl & 3;
    const int blh  = (bl >> 4) & 1;        // rotation for q
    const int nb0  = (tid >> 5) << 1;
    const int bcol0 = bx * 128;

    float acc[4][4][4];
#pragma unroll
    for (int mi = 0; mi < 4; mi++)
#pragma unroll
        for (int ni = 0; ni < 4; ni++)
#pragma unroll
            for (int q = 0; q < 4; q++) acc[mi][ni][q] = 0.f;

    uint32_t paH[8];   // A k-pairs, prepacked half2
    uint32_t pbH[8];   // B (j,nbi) units, prepacked half2

    // prefetch tile 0 (pack at load)
#pragma unroll
    for (int tt = 0; tt < 4; tt++) {
        const float4 v = *(const float4*)(Ag + tt * 4);
        paH[tt * 2 + 0] = pack_h2(v.x, v.y);
        paH[tt * 2 + 1] = pack_h2(v.z, v.w);
    }
#pragma unroll
    for (int j = 0; j < 4; j++) {
        const int ppq4 = (j + blh) & 3;
        const int p = ppq4 * 4 + bppl;
#pragma unroll
        for (int nbi = 0; nbi < 2; nbi++) {
            const int n = (nb0 + nbi) * 8 + bnn;
            pbH[j * 2 + nbi] = pack_h2(B[(size_t)(2 * p) * ldb + bcol0 + n],
                                       B[(size_t)(2 * p + 1) * ldb + bcol0 + n]);
        }
    }
    // stage tile 0 -> buf 0
#pragma unroll
    for (int j = 0; j < 8; j++) {
        const int pp2 = (j + ac) & 7;
        As[0][abase + ((pp2 & 3) << 2) + ((pp2 >> 2) << 1)] = paH[pp2];
    }
#pragma unroll
    for (int j = 0; j < 4; j++) {
        const int ppq4 = (j + blh) & 3;
        const int ks = ppq4 >> 1, q = ppq4 & 1;
#pragma unroll
        for (int nbi = 0; nbi < 2; nbi++) {
            const int nb = nb0 + nbi;
            Bs[0][(((ks * 16 + nb) * 32 + bl) << 1) + q] = pbH[j * 2 + nbi];
        }
    }
    __syncthreads();

    const int NT = K >> 5;
    for (int T = 0; T < NT; T++) {
        const int buf = T & 1;
        if (T + 1 < NT) {
            const int off = (T + 1) << 5;
#pragma unroll
            for (int tt = 0; tt < 4; tt++) {
                const float4 v = *(const float4*)(Ag + off + tt * 4);
                paH[tt * 2 + 0] = pack_h2(v.x, v.y);
                paH[tt * 2 + 1] = pack_h2(v.z, v.w);
            }
#pragma unroll
            for (int j = 0; j < 4; j++) {
                const int ppq4 = (j + blh) & 3;
                const int p = ppq4 * 4 + bppl;
#pragma unroll
                for (int nbi = 0; nbi < 2; nbi++) {
                    const int n = (nb0 + nbi) * 8 + bnn;
                    pbH[j * 2 + nbi] = pack_h2(B[(size_t)(off + 2 * p) * ldb + bcol0 + n],
                                               B[(size_t)(off + 2 * p + 1) * ldb + bcol0 + n]);
                }
            }
        }
        // compute: 2 k16 steps, 16 mma each
#pragma unroll
        for (int ks = 0; ks < 2; ks++) {
            uint32_t afr[4][4], bfr[4][2];
#pragma unroll
            for (int mi = 0; mi < 4; mi++) {
                const uint4 v = *(const uint4*)&As[buf][(((ks * 8 + wr * 4 + mi) * 32 + lane) << 2)];
                afr[mi][0] = v.x; afr[mi][1] = v.y; afr[mi][2] = v.z; afr[mi][3] = v.w;
            }
#pragma unroll
            for (int ni = 0; ni < 4; ni++) {
                const uint2 v = *(const uint2*)&Bs[buf][(((ks * 16 + wc * 4 + ni) * 32 + lane) << 1)];
                bfr[ni][0] = v.x; bfr[ni][1] = v.y;
            }
#pragma unroll
            for (int mi = 0; mi < 4; mi++)
#pragma unroll
                for (int ni = 0; ni < 4; ni++)
                    mma_f16(acc[mi][ni], afr[mi], bfr[ni]);
        }
        // stage next tile -> other buffer
        if (T + 1 < NT) {
            const int nb2 = buf ^ 1;
#pragma unroll
            for (int j = 0; j < 8; j++) {
                const int pp2 = (j + ac) & 7;
                As[nb2][abase + ((pp2 & 3) << 2) + ((pp2 >> 2) << 1)] = paH[pp2];
            }
#pragma unroll
            for (int j = 0; j < 4; j++) {
                const int ppq4 = (j + blh) & 3;
                const int ks = ppq4 >> 1, q = ppq4 & 1;
#pragma unroll
                for (int nbi = 0; nbi < 2; nbi++) {
                    const int nb = nb0 + nbi;
                    Bs[nb2][(((ks * 16 + nb) * 32 + bl) << 1) + q] = pbH[j * 2 + nbi];
                }
            }
        }
        __syncthreads();
    }

    const int g = lane >> 2;
    const int t = lane & 3;
#pragma unroll
    for (int mi = 0; mi < 4; mi++) {
        const int r0 = by * 128 + wr * 64 + mi * 16 + g;
#pragma unroll
        for (int ni = 0; ni < 4; ni++) {
            const int c0 = bx * 128 + wc * 32 + ni * 8 + t * 2;
            float b0 = 0.f, b1 = 0.f;
            if (bias) { b0 = bias[c0]; b1 = bias[c0 + 1]; }
            float2 o0, o1;
            o0.x = acc[mi][ni][0] + b0; o0.y = acc[mi][ni][1] + b1;
            o1.x = acc[mi][ni][2] + b0; o1.y = acc[mi][ni][3] + b1;
            if (relu) {
                o0.x = fmaxf(o0.x, 0.f); o0.y = fmaxf(o0.y, 0.f);
                o1.x = fmaxf(o1.x, 0.f); o1.y = fmaxf(o1.y, 0.f);
            }
            *(float2*)&C[(size_t)r0 * ldc + c0] = o0;
            *(float2*)&C[(size_t)(r0 + 8) * ldc + c0] = o1;
        }
    }
}

// ---------------- tensor-core fused rel-attention (pitch-68 + E-band skip) ----
#define AT_QW 0                     /* 64x68 tf32 */
#define AT_QR 4352
#define AT_K  8704
#define AT_R  13056                 /* 128x68 (127 used) */
#define AT_V  21760
#define AT_S  26112                 /* 64x68 f32 */
#define AT_E  30464                 /* 64x136 f32 */
#define AT_P  39168                 /* 64x68 tf32 */
#define AT_M  43520
#define AT_L  43584
#define AT_A  43648
#define ATTN2_SMEM_FLOATS 43712
#define ATTN2_SMEM_BYTES  (ATTN2_SMEM_FLOATS * 4)

__global__ __launch_bounds__(256) void attn_mma_kernel(
    const float* __restrict__ wh, const float* __restrict__ rh,
    const float* __restrict__ rwb, const float* __restrict__ rrb,
    float* __restrict__ av)
{
    extern __shared__ float smf[];
    uint32_t* sQw = (uint32_t*)(smf + AT_QW);
    uint32_t* sQr = (uint32_t*)(smf + AT_QR);
    uint32_t* sK  = (uint32_t*)(smf + AT_K);
    uint32_t* sR  = (uint32_t*)(smf + AT_R);
    uint32_t* sV  = (uint32_t*)(smf + AT_V);
    float*    sS  = smf + AT_S;
    float*    sE  = smf + AT_E;
    uint32_t* sP  = (uint32_t*)(smf + AT_P);
    float*    sM  = smf + AT_M;
    float*    sL  = smf + AT_L;
    float*    sA  = smf + AT_A;

    const int i0 = (15 - blockIdx.x) << 6;   // heaviest q-tile first
    const int bi = blockIdx.y >> 4;
    const int hn = blockIdx.y & 15;
    const int tid = threadIdx.x;
    const int lane = tid & 31;
    const int w = tid >> 5;
    const int rb = w >> 1;           // 0..3
    const int ch = w & 1;            // 0..1
    const int g = lane >> 2;         // 0..7
    const int t = lane & 3;          // 0..3
    const int hbase = hn << 6;

    // E diagonal-band block bounds for this warp (rows 16rb..16rb+15, col half ch)
    int ebmin = 41 - 16 * rb - 64 * ch;
    ebmin = ebmin <= 0 ? 0 : ((ebmin + 7) >> 3);
    int ebmax = (126 - 16 * rb - 64 * ch) >> 3;
    if (ebmax > 7) ebmax = 7;

    // staging lane coords (float4 granularity)
    const int svr = tid >> 4;             // row 0..15 base (of 64, via +u*16)
    const int svc = (tid & 15) << 2;      // col 0,4,..,60

    // ---- load Q tiles (bias folded), vectorized ----
    {
        float4 w4 = *(const float4*)&rwb[hbase + svc];
        float4 r4 = *(const float4*)&rrb[hbase + svc];
#pragma unroll
        for (int u = 0; u < 4; u++) {
            const int r = svr + u * 16;
            const size_t base = ((size_t)((MLEN + i0 + r) * BSZ + bi)) * 3072 + hbase + svc;
            float4 q4 = *(const float4*)&wh[base];
            float4 aw = make_float4(q4.x + w4.x, q4.y + w4.y, q4.z + w4.z, q4.w + w4.w);
            float4 ar = make_float4(q4.x + r4.x, q4.y + r4.y, q4.z + r4.z, q4.w + r4.w);
            *(uint4*)&sQw[r * 68 + svc] = cvt4(aw);
            *(uint4*)&sQr[r * 68 + svc] = cvt4(ar);
        }
    }
    if (tid < 64) { sM[tid] = -3e38f; sL[tid] = 0.f; }

    float acc[4][4];   // PV accum frags
#pragma unroll
    for (int cb = 0; cb < 4; cb++)
#pragma unroll
        for (int q = 0; q < 4; q++) acc[cb][q] = 0.f;

    const int arow0 = (16 * rb + g) * 68;
    const int arow1 = (16 * rb + g + 8) * 68;
    const int nkt = 17 + (i0 >> 6);

    // K/V prefetch registers for tile 0
    float4 pk[4], pv[4];
#pragma unroll
    for (int u = 0; u < 4; u++) {
        const int r = svr + u * 16;
        const size_t base = ((size_t)(r * BSZ + bi)) * 3072 + hbase + svc;
        pk[u] = *(const float4*)&wh[base + 1024];
        pv[u] = *(const float4*)&wh[base + 2048];
    }

    for (int kt = 0; kt < nkt; kt++) {
        const int j0 = kt << 6;
        __syncthreads();
        // ---- store prefetched K/V; stage R directly ----
#pragma unroll
        for (int u = 0; u < 4; u++) {
            const int r = svr + u * 16;
            *(uint4*)&sK[r * 68 + svc] = cvt4(pk[u]);
            *(uint4*)&sV[r * 68 + svc] = cvt4(pv[u]);
        }
        const int rbase = j0 + MLEN - 1 - i0 - 63;
#pragma unroll
        for (int u = 0; u < 8; u++) {
            const int idx = tid + u * 256;
            if (idx < 2032) {
                const int r = idx >> 4, c4 = (idx & 15) << 2;
                int rg = rbase + r;
                rg = rg < 0 ? 0 : (rg > KLEN - 1 ? KLEN - 1 : rg);
                const float4 v = *(const float4*)&rh[(size_t)rg * DIM + hbase + c4];
                *(uint4*)&sR[r * 68 + c4] = cvt4(v);
            }
        }
        __syncthreads();

        // ---- prefetch next tile's K/V (overlaps mma below) ----
        if (kt + 1 < nkt) {
#pragma unroll
            for (int u = 0; u < 4; u++) {
                const int r = svr + u * 16;
                const size_t base = ((size_t)(((j0 + 64) + r) * BSZ + bi)) * 3072 + hbase + svc;
                pk[u] = *(const float4*)&wh[base + 1024];
                pv[u] = *(const float4*)&wh[base + 2048];
            }
        }

        // ---- S and E via mma (E restricted to diagonal band blocks) ----
        float Sacc[4][4], Eacc[8][4];
#pragma unroll
        for (int cb = 0; cb < 4; cb++)
#pragma unroll
            for (int q = 0; q < 4; q++) Sacc[cb][q] = 0.f;
#pragma unroll
        for (int eb = 0; eb < 8; eb++)
#pragma unroll
            for (int q = 0; q < 4; q++) Eacc[eb][q] = 0.f;

#pragma unroll
        for (int ks = 0; ks < 8; ks++) {
            const int kc = ks * 8 + t;
            uint32_t aw[4], ar[4];
            aw[0] = sQw[arow0 + kc]; aw[1] = sQw[arow1 + kc];
            aw[2] = sQw[arow0 + kc + 4]; aw[3] = sQw[arow1 + kc + 4];
            ar[0] = sQr[arow0 + kc]; ar[1] = sQr[arow1 + kc];
            ar[2] = sQr[arow0 + kc + 4]; ar[3] = sQr[arow1 + kc + 4];
#pragma unroll
            for (int cb = 0; cb < 4; cb++) {
                const int kr = (8 * (ch * 4 + cb) + g) * 68 + kc;
                uint32_t b[2] = { sK[kr], sK[kr + 4] };
                mma_tf32(Sacc[cb], aw, b);
            }
#pragma unroll
            for (int eb = 0; eb < 8; eb++) {
                if (eb >= ebmin && eb <= ebmax) {
                    const int rr = (8 * (ch * 8 + eb) + g) * 68 + kc;
                    uint32_t b[2] = { sR[rr], sR[rr + 4] };
                    mma_tf32(Eacc[eb], ar, b);
                }
            }
        }
        // write S, E to smem (float2 stores)
#pragma unroll
        for (int cb = 0; cb < 4; cb++) {
            const int col = 8 * (ch * 4 + cb) + 2 * t;
            *(float2*)&sS[(16 * rb + g) * 68 + col]     = make_float2(Sacc[cb][0], Sacc[cb][1]);
            *(float2*)&sS[(16 * rb + g + 8) * 68 + col] = make_float2(Sacc[cb][2], Sacc[cb][3]);
        }
#pragma unroll
        for (int eb = 0; eb < 8; eb++) {
            if (eb >= ebmin && eb <= ebmax) {
                const int col = 8 * (ch * 8 + eb) + 2 * t;
                *(float2*)&sE[(16 * rb + g) * 136 + col]     = make_float2(Eacc[eb][0], Eacc[eb][1]);
                *(float2*)&sE[(16 * rb + g + 8) * 136 + col] = make_float2(Eacc[eb][2], Eacc[eb][3]);
            }
        }
        __syncthreads();

        // ---- online softmax: warp w owns rows w*8..w*8+7; lane quad per row ----
        {
            const int row = w * 8 + g;
            const int qi = i0 + row;
            float sarr[16];
            {
                const float4* srow = (const float4*)&sS[row * 68 + t * 16];
#pragma unroll
                for (int v4 = 0; v4 < 4; v4++) {
                    float4 s4 = srow[v4];
                    sarr[v4 * 4 + 0] = s4.x; sarr[v4 * 4 + 1] = s4.y;
                    sarr[v4 * 4 + 2] = s4.z; sarr[v4 * 4 + 3] = s4.w;
                }
            }
            const int ebase = row * 135 + t * 16 + 63;   // row*136 + (t*16 - row + 63)
            float tmax = -3e38f;
#pragma unroll
            for (int e = 0; e < 16; e++) {
                float vv = (sarr[e] + sE[ebase + e]) * 0.125f;
                if (j0 + t * 16 + e > MLEN + qi) vv = -3e38f;
                sarr[e] = vv;
                tmax = fmaxf(tmax, vv);
            }
            tmax = fmaxf(tmax, __shfl_xor_sync(0xffffffffu, tmax, 1));
            tmax = fmaxf(tmax, __shfl_xor_sync(0xffffffffu, tmax, 2));
            const float mold = sM[row];
            const float mnew = fmaxf(mold, tmax);
            float rsum = 0.f;
            uint32_t pb[16];
#pragma unroll
            for (int e = 0; e < 16; e++) {
                float p = __expf(sarr[e] - mnew);
                rsum += p;
                pb[e] = f2tf32(p);
            }
            rsum += __shfl_xor_sync(0xffffffffu, rsum, 1);
            rsum += __shfl_xor_sync(0xffffffffu, rsum, 2);
            if (t == 0) {
                const float al = __expf(mold - mnew);
                sM[row] = mnew;
                sA[row] = al;
                sL[row] = sL[row] * al + rsum;
            }
            uint4* pd = (uint4*)&sP[row * 68 + t * 16];
            pd[0] = make_uint4(pb[0], pb[1], pb[2], pb[3]);
            pd[1] = make_uint4(pb[4], pb[5], pb[6], pb[7]);
            pd[2] = make_uint4(pb[8], pb[9], pb[10], pb[11]);
            pd[3] = make_uint4(pb[12], pb[13], pb[14], pb[15]);
        }
        __syncthreads();

        // ---- rescale + P@V via mma ----
        {
            const float al0 = sA[16 * rb + g];
            const float al1 = sA[16 * rb + g + 8];
#pragma unroll
            for (int cb = 0; cb < 4; cb++) {
                acc[cb][0] *= al0; acc[cb][1] *= al0;
                acc[cb][2] *= al1; acc[cb][3] *= al1;
            }
            const int prow0 = (16 * rb + g) * 68;
            const int prow1 = (16 * rb + g + 8) * 68;
#pragma unroll
            for (int ks = 0; ks < 8; ks++) {
                const int kc = ks * 8 + t;
                uint32_t a[4] = { sP[prow0 + kc], sP[prow1 + kc],
                                  sP[prow0 + kc + 4], sP[prow1 + kc + 4] };
#pragma unroll
                for (int cb = 0; cb < 4; cb++) {
                    const int col = 8 * (ch * 4 + cb) + g;
                    uint32_t b[2] = { sV[(ks * 8 + t) * 68 + col],
                                      sV[(ks * 8 + t + 4) * 68 + col] };
                    mma_tf32(acc[cb], a, b);
                }
            }
        }
    }

    // ---- finalize ----
    const float linv0 = 1.f / sL[16 * rb + g];
    const float linv1 = 1.f / sL[16 * rb + g + 8];
    const int r0 = i0 + 16 * rb + g;
#pragma unroll
    for (int cb = 0; cb < 4; cb++) {
        const int col = hbase + 8 * (ch * 4 + cb) + 2 * t;
        float2 o0, o1;
        o0.x = acc[cb][0] * linv0; o0.y = acc[cb][1] * linv0;
        o1.x = acc[cb][2] * linv1; o1.y = acc[cb][3] * linv1;
        *(float2*)&av[((size_t)(r0 * BSZ + bi)) * DIM + col] = o0;
        *(float2*)&av[((size_t)((r0 + 8) * BSZ + bi)) * DIM + col] = o1;
    }
}

// ---------------- residual + layernorm (row per block) ----------------
__global__ __launch_bounds__(256) void ln_kernel(
    const float* __restrict__ x, const float* __restrict__ res,
    const float* __restrict__ g, const float* __restrict__ b,
    float* __restrict__ out1, float* __restrict__ out2)
{
    const int row = blockIdx.x;
    const int tid = threadIdx.x;
    float4 xv = *(const float4*)(x + (size_t)row * DIM + tid * 4);
    float4 rv = *(const float4*)(res + (size_t)row * DIM + tid * 4);
    float v0 = xv.x + rv.x, v1 = xv.y + rv.y, v2 = xv.z + rv.z, v3 = xv.w + rv.w;
    float s = v0 + v1 + v2 + v3;
    float q = v0 * v0 + v1 * v1 + v2 * v2 + v3 * v3;
#pragma unroll
    for (int off = 16; off > 0; off >>= 1) {
        s += __shfl_xor_sync(0xffffffffu, s, off);
        q += __shfl_xor_sync(0xffffffffu, q, off);
    }
    __shared__ float sb[8], qb[8];
    const int w = tid >> 5, lane = tid & 31;
    if (lane == 0) { sb[w] = s; qb[w] = q; }
    __syncthreads();
    if (w == 0) {
        float s2 = (lane < 8) ? sb[lane] : 0.f;
        float q2 = (lane < 8) ? qb[lane] : 0.f;
#pragma unroll
        for (int off = 4; off > 0; off >>= 1) {
            s2 += __shfl_xor_sync(0xffffffffu, s2, off);
            q2 += __shfl_xor_sync(0xffffffffu, q2, off);
        }
        if (lane == 0) { sb[0] = s2; qb[0] = q2; }
    }
    __syncthreads();
    const float mean = sb[0] * (1.0f / DIM);
    const float var  = qb[0] * (1.0f / DIM) - mean * mean;
    const float rstd = rsqrtf(var + 1e-5f);
    float4 gv = *(const float4*)(g + tid * 4);
    float4 bv = *(const float4*)(b + tid * 4);
    float4 o;
    o.x = (v0 - mean) * rstd * gv.x + bv.x;
    o.y = (v1 - mean) * rstd * gv.y + bv.y;
    o.z = (v2 - mean) * rstd * gv.z + bv.z;
    o.w = (v3 - mean) * rstd * gv.w + bv.w;
    *(float4*)(out1 + (size_t)row * DIM + tid * 4) = o;
    if (out2) *(float4*)(out2 + (size_t)row * DIM + tid * 4) = o;
}

// ---------------- host orchestration ----------------
extern "C" void kernel_launch(void* const* d_in, const int* in_sizes, int n_in,
                              void* d_out, int out_size) {
    const float* mems = (const float*)d_in[0];
    const float* raw  = (const float*)d_in[1];
    /* d_in[2] = attention_mask: analytic, ignored */
    const float* rwb  = (const float*)d_in[3];
    const float* rrb  = (const float*)d_in[4];
    const float* qkvw = (const float*)d_in[5];
    const float* rw   = (const float*)d_in[6];
    const float* ow   = (const float*)d_in[7];
    const float* ln1g = (const float*)d_in[8];
    const float* ln1b = (const float*)d_in[9];
    const float* fw1  = (const float*)d_in[10];
    const float* fb1  = (const float*)d_in[11];
    const float* fw2  = (const float*)d_in[12];
    const float* fb2  = (const float*)d_in[13];
    const float* ln2g = (const float*)d_in[14];
    const float* ln2b = (const float*)d_in[15];
    float* out = (float*)d_out;

    const bool full_out = out_size >= (NLAY + 2) * NE;   // core + new_mems(5 slabs)
    float* out_mems = full_out ? out + NE : nullptr;

    float *wh, *pos, *rh, *av, *tmp, *core, *core2, *ff;
    cudaGetSymbolAddress((void**)&wh,   g_wheads);
    cudaGetSymbolAddress((void**)&pos,  g_pos);
    cudaGetSymbolAddress((void**)&rh,   g_rhead);
    cudaGetSymbolAddress((void**)&av,   g_attnvec);
    cudaGetSymbolAddress((void**)&tmp,  g_tmp);
    cudaGetSymbolAddress((void**)&core, g_core);
    cudaGetSymbolAddress((void**)&core2,g_core2);
    cudaGetSymbolAddress((void**)&ff,   g_ff);

    cudaFuncSetAttribute((const void*)attn_mma_kernel,
                         cudaFuncAttributeMaxDynamicSharedMemorySize, ATTN2_SMEM_BYTES);

    const int C4 = NE / 4;               // float4 count per slab
    const int CB = (C4 + 255) / 256;

    copy_kernel<<<CB, 256>>>(core, raw, C4);
    if (out_mems) copy_kernel<<<CB, 256>>>(out_mems, raw, C4);
    pos_kernel<<<(KLEN * DIM + 255) / 256, 256>>>(pos);

    for (int i = 0; i < NLAY; i++) {
        // QKV split, reading sources directly (no cat buffer):
        //  - mem rows (from mems[i]) need only K,V (cols 1024..3071)
        //  - q rows (from core) need all 3072 cols
        mma_gemm<<<dim3(16, 16), 256>>>(
            mems + (size_t)i * NE, qkvw + (size_t)i * DIM * 3 * DIM + 1024, wh + 1024,
            2048, 2048, 1024, 1024, 3072, 3072, nullptr, 0);
        mma_gemm<<<dim3(24, 16), 256>>>(
            core, qkvw + (size_t)i * DIM * 3 * DIM,
            wh + (size_t)2048 * 3072,
            2048, 3072, 1024, 1024, 3072, 3072, nullptr, 0);
        mma_gemm<<<dim3(8, 16), 256>>>(
            pos, rw + (size_t)i * DIM * DIM, rh,
            2048, 1024, 1024, 1024, 1024, 1024, nullptr, 0);

        attn_mma_kernel<<<dim3(16, 32), 256, ATTN2_SMEM_BYTES>>>(wh, rh, rwb, rrb, av);

        mma_gemm<<<dim3(8, 16), 256>>>(
            av, ow + (size_t)i * DIM * DIM, tmp,
            2048, 1024, 1024, 1024, 1024, 1024, nullptr, 0);
        ln_kernel<<<2048, 256>>>(tmp, core, ln1g + i * DIM, ln1b + i * DIM, core2, nullptr);

        mma_gemm<<<dim3(8, 16), 256>>>(
            core2, fw1 + (size_t)i * DIM * DIM, ff,
            2048, 1024, 1024, 1024, 1024, 1024, fb1 + i * DIM, 1);
        mma_gemm<<<dim3(8, 16), 256>>>(
            ff, fw2 + (size_t)i * DIM * DIM, tmp,
            2048, 1024, 1024, 1024, 1024, 1024, fb2 + i * DIM, 0);
        float* lnDst = (i == NLAY - 1) ? out : core;
        ln_kernel<<<2048, 256>>>(tmp, core2, ln2g + i * DIM, ln2b + i * DIM, lnDst,
                                 out_mems ? out_mems + (size_t)(i + 1) * NE : nullptr);
    }
}

// round 14
// speedup vs baseline: 1.4707x; 1.1279x over previous
#include <cuda_runtime.h>
#include <cuda_fp16.h>
#include <math.h>
#include <stdint.h>

#define L_Q   1024
#define BSZ   2
#define DIM   1024
#define NHEAD 16
#define DHEAD 64
#define NLAY  4
#define MLEN  1024
#define KLEN  2048
#define NE    (L_Q*BSZ*DIM)   /* 2097152 floats per (L,B,D) slab */

// ---------------- scratch (device globals; no allocation allowed) ----------------
__device__ float g_wheads[(size_t)KLEN*BSZ*3*DIM];   // 50 MB
__device__ float g_pos[(size_t)KLEN*DIM];            // 8 MB
__device__ float g_rhead[(size_t)KLEN*DIM];          // 8 MB
__device__ float g_attnvec[NE];
__device__ float g_tmp[NE];
__device__ float g_core[NE];
__device__ float g_core2[NE];
__device__ float g_ff[NE];

// ---------------- simple float4 copy ----------------
__global__ void copy_kernel(float* __restrict__ dst, const float* __restrict__ src, int n4) {
    int i = blockIdx.x * blockDim.x + threadIdx.x;
    if (i < n4) ((float4*)dst)[i] = ((const float4*)src)[i];
}

// ---------------- positional embedding ----------------
__global__ void pos_kernel(float* __restrict__ pos) {
    int idx = blockIdx.x * blockDim.x + threadIdx.x;
    if (idx >= KLEN * DIM) return;
    int j = idx >> 10;           // 0..2047
    int i = idx & 1023;          // 0..1023
    int t = i & 511;
    float x = (float)(2 * t) * (1.0f / 1024.0f);
    float invf = expf(-x * 9.210340371976184f);   // 10000^{-x}
    float arg = (float)(KLEN - 1 - j) * invf;
    pos[idx] = (i < 512) ? sinf(arg) : cosf(arg);
}

// ---------------- helpers ----------------
__device__ __forceinline__ uint32_t f2tf32(float f) {
    uint32_t u;
    asm("cvt.rna.tf32.f32 %0, %1;" : "=r"(u) : "f"(f));
    return u;
}
__device__ __forceinline__ uint4 cvt4(float4 v) {
    return make_uint4(f2tf32(v.x), f2tf32(v.y), f2tf32(v.z), f2tf32(v.w));
}
__device__ __forceinline__ void mma_tf32(float* c, const uint32_t* a, const uint32_t* b) {
    asm volatile(
        "mma.sync.aligned.m16n8k8.row.col.f32.tf32.tf32.f32 "
        "{%0,%1,%2,%3}, {%4,%5,%6,%7}, {%8,%9}, {%0,%1,%2,%3};"
        : "+f"(c[0]), "+f"(c[1]), "+f"(c[2]), "+f"(c[3])
        : "r"(a[0]), "r"(a[1]), "r"(a[2]), "r"(a[3]), "r"(b[0]), "r"(b[1]));
}
// pack (lo,hi) floats -> half2 bits (lo in low half)
__device__ __forceinline__ uint32_t pack_h2(float lo, float hi) {
    uint32_t r;
    asm("cvt.rn.f16x2.f32 %0, %1, %2;" : "=r"(r) : "f"(hi), "f"(lo));
    return r;
}
__device__ __forceinline__ uint2 pack4(float4 v) {
    return make_uint2(pack_h2(v.x, v.y), pack_h2(v.z, v.w));
}
__device__ __forceinline__ void mma_f16(float* c, const uint32_t* a, const uint32_t* b) {
    asm volatile(
        "mma.sync.aligned.m16n8k16.row.col.f32.f16.f16.f32 "
        "{%0,%1,%2,%3}, {%4,%5,%6,%7}, {%8,%9}, {%0,%1,%2,%3};"
        : "+f"(c[0]), "+f"(c[1]), "+f"(c[2]), "+f"(c[3])
        : "r"(a[0]), "r"(a[1]), "r"(a[2]), "r"(a[3]), "r"(b[0]), "r"(b[1]));
}

// ---------------- fp16 tensor-core GEMM: 128x128 block, K-tile 32, 2-stage ----
__global__ __launch_bounds__(256, 2) void mma_gemm(
    const float* __restrict__ A, const float* __restrict__ B, float* __restrict__ C,
    int M, int N, int K, int lda, int ldb, int ldc,
    const float* __restrict__ bias, int relu)
{
    __shared__ __align__(16) uint32_t As[2][2048];
    __shared__ __align__(16) uint32_t Bs[2][2048];

    const int tid = threadIdx.x;
    const int lane = tid & 31;
    const int w = tid >> 5;
    const int wr = w & 1;            // 0..1 (m 64-half)
    const int wc = w >> 1;           // 0..3 (n 32-quarter)
    const int bx = blockIdx.x, by = blockIdx.y;

    const int ar  = tid >> 1;              // 0..127
    const int kh  = tid & 1;               // k 0..15 or 16..31
    const int ac  = ((ar >> 1) & 3) + 4 * kh;   // rotation class
    const int abase = (((kh * 8 + (ar >> 4)) * 32 + (ar & 7) * 4) << 2) + ((ar >> 3) & 1);
    const float* Ag = A + (size_t)(by * 128 + ar) * lda + kh * 16;

    const int bl   = lane;
    const int bnn  = bl >> 2;
    const int bppl = bl & 3;
    const int blh  = (bl >> 4) & 1;        // rotation for q
    const int nb0  = (tid >> 5) << 1;
    const int bcol0 = bx * 128;

    float acc[4][4][4];
#pragma unroll
    for (int mi = 0; mi < 4; mi++)
#pragma unroll
        for (int ni = 0; ni < 4; ni++)
#pragma unroll
            for (int q = 0; q < 4; q++) acc[mi][ni][q] = 0.f;

    uint32_t paH[8];
    uint32_t pbH[8];

#pragma unroll
    for (int tt = 0; tt < 4; tt++) {
        const float4 v = *(const float4*)(Ag + tt * 4);
        paH[tt * 2 + 0] = pack_h2(v.x, v.y);
        paH[tt * 2 + 1] = pack_h2(v.z, v.w);
    }
#pragma unroll
    for (int j = 0; j < 4; j++) {
        const int ppq4 = (j + blh) & 3;
        const int p = ppq4 * 4 + bppl;
#pragma unroll
        for (int nbi = 0; nbi < 2; nbi++) {
            const int n = (nb0 + nbi) * 8 + bnn;
            pbH[j * 2 + nbi] = pack_h2(B[(size_t)(2 * p) * ldb + bcol0 + n],
                                       B[(size_t)(2 * p + 1) * ldb + bcol0 + n]);
        }
    }
#pragma unroll
    for (int j = 0; j < 8; j++) {
        const int pp2 = (j + ac) & 7;
        As[0][abase + ((pp2 & 3) << 2) + ((pp2 >> 2) << 1)] = paH[pp2];
    }
#pragma unroll
    for (int j = 0; j < 4; j++) {
        const int ppq4 = (j + blh) & 3;
        const int ks = ppq4 >> 1, q = ppq4 & 1;
#pragma unroll
        for (int nbi = 0; nbi < 2; nbi++) {
            const int nb = nb0 + nbi;
            Bs[0][(((ks * 16 + nb) * 32 + bl) << 1) + q] = pbH[j * 2 + nbi];
        }
    }
    __syncthreads();

    const int NT = K >> 5;
    for (int T = 0; T < NT; T++) {
        const int buf = T & 1;
        if (T + 1 < NT) {
            const int off = (T + 1) << 5;
#pragma unroll
            for (int tt = 0; tt < 4; tt++) {
                const float4 v = *(const float4*)(Ag + off + tt * 4);
                paH[tt * 2 + 0] = pack_h2(v.x, v.y);
                paH[tt * 2 + 1] = pack_h2(v.z, v.w);
            }
#pragma unroll
            for (int j = 0; j < 4; j++) {
                const int ppq4 = (j + blh) & 3;
                const int p = ppq4 * 4 + bppl;
#pragma unroll
                for (int nbi = 0; nbi < 2; nbi++) {
                    const int n = (nb0 + nbi) * 8 + bnn;
                    pbH[j * 2 + nbi] = pack_h2(B[(size_t)(off + 2 * p) * ldb + bcol0 + n],
                                               B[(size_t)(off + 2 * p + 1) * ldb + bcol0 + n]);
                }
            }
        }
#pragma unroll
        for (int ks = 0; ks < 2; ks++) {
            uint32_t afr[4][4], bfr[4][2];
#pragma unroll
            for (int mi = 0; mi < 4; mi++) {
                const uint4 v = *(const uint4*)&As[buf][(((ks * 8 + wr * 4 + mi) * 32 + lane) << 2)];
                afr[mi][0] = v.x; afr[mi][1] = v.y; afr[mi][2] = v.z; afr[mi][3] = v.w;
            }
#pragma unroll
            for (int ni = 0; ni < 4; ni++) {
                const uint2 v = *(const uint2*)&Bs[buf][(((ks * 16 + wc * 4 + ni) * 32 + lane) << 1)];
                bfr[ni][0] = v.x; bfr[ni][1] = v.y;
            }
#pragma unroll
            for (int mi = 0; mi < 4; mi++)
#pragma unroll
                for (int ni = 0; ni < 4; ni++)
                    mma_f16(acc[mi][ni], afr[mi], bfr[ni]);
        }
        if (T + 1 < NT) {
            const int nb2 = buf ^ 1;
#pragma unroll
            for (int j = 0; j < 8; j++) {
                const int pp2 = (j + ac) & 7;
                As[nb2][abase + ((pp2 & 3) << 2) + ((pp2 >> 2) << 1)] = paH[pp2];
            }
#pragma unroll
            for (int j = 0; j < 4; j++) {
                const int ppq4 = (j + blh) & 3;
                const int ks = ppq4 >> 1, q = ppq4 & 1;
#pragma unroll
                for (int nbi = 0; nbi < 2; nbi++) {
                    const int nb = nb0 + nbi;
                    Bs[nb2][(((ks * 16 + nb) * 32 + bl) << 1) + q] = pbH[j * 2 + nbi];
                }
            }
        }
        __syncthreads();
    }

    const int g = lane >> 2;
    const int t = lane & 3;
#pragma unroll
    for (int mi = 0; mi < 4; mi++) {
        const int r0 = by * 128 + wr * 64 + mi * 16 + g;
#pragma unroll
        for (int ni = 0; ni < 4; ni++) {
            const int c0 = bx * 128 + wc * 32 + ni * 8 + t * 2;
            float b0 = 0.f, b1 = 0.f;
            if (bias) { b0 = bias[c0]; b1 = bias[c0 + 1]; }
            float2 o0, o1;
            o0.x = acc[mi][ni][0] + b0; o0.y = acc[mi][ni][1] + b1;
            o1.x = acc[mi][ni][2] + b0; o1.y = acc[mi][ni][3] + b1;
            if (relu) {
                o0.x = fmaxf(o0.x, 0.f); o0.y = fmaxf(o0.y, 0.f);
                o1.x = fmaxf(o1.x, 0.f); o1.y = fmaxf(o1.y, 0.f);
            }
            *(float2*)&C[(size_t)r0 * ldc + c0] = o0;
            *(float2*)&C[(size_t)(r0 + 8) * ldc + c0] = o1;
        }
    }
}

// ---------------- tensor-core fused rel-attention ----------------
// fp16 S/E phase (pitch-36 half2 tiles), tf32 PV phase (pitch-68), E-band skip.
#define AT_QW 0                     /* 64x36 half2 */
#define AT_QR 2304
#define AT_K  4608
#define AT_R  6912                  /* 128x36 half2 (127 used) */
#define AT_V  11520                 /* 64x68 tf32 */
#define AT_S  15872                 /* 64x68 f32 */
#define AT_E  20224                 /* 64x136 f32 */
#define AT_P  28928                 /* 64x68 tf32 */
#define AT_M  33280
#define AT_L  33344
#define AT_A  33408
#define ATTN2_SMEM_FLOATS 33472
#define ATTN2_SMEM_BYTES  (ATTN2_SMEM_FLOATS * 4)

__global__ __launch_bounds__(256) void attn_mma_kernel(
    const float* __restrict__ wh, const float* __restrict__ rh,
    const float* __restrict__ rwb, const float* __restrict__ rrb,
    float* __restrict__ av)
{
    extern __shared__ float smf[];
    uint32_t* sQw = (uint32_t*)(smf + AT_QW);
    uint32_t* sQr = (uint32_t*)(smf + AT_QR);
    uint32_t* sK  = (uint32_t*)(smf + AT_K);
    uint32_t* sR  = (uint32_t*)(smf + AT_R);
    uint32_t* sV  = (uint32_t*)(smf + AT_V);
    float*    sS  = smf + AT_S;
    float*    sE  = smf + AT_E;
    uint32_t* sP  = (uint32_t*)(smf + AT_P);
    float*    sM  = smf + AT_M;
    float*    sL  = smf + AT_L;
    float*    sA  = smf + AT_A;

    const int i0 = (15 - blockIdx.x) << 6;   // heaviest q-tile first
    const int bi = blockIdx.y >> 4;
    const int hn = blockIdx.y & 15;
    const int tid = threadIdx.x;
    const int lane = tid & 31;
    const int w = tid >> 5;
    const int rb = w >> 1;           // 0..3
    const int ch = w & 1;            // 0..1
    const int g = lane >> 2;         // 0..7
    const int t = lane & 3;          // 0..3
    const int hbase = hn << 6;

    // E diagonal-band block bounds for this warp (rows 16rb..16rb+15, col half ch)
    int ebmin = 41 - 16 * rb - 64 * ch;
    ebmin = ebmin <= 0 ? 0 : ((ebmin + 7) >> 3);
    int ebmax = (126 - 16 * rb - 64 * ch) >> 3;
    if (ebmax > 7) ebmax = 7;

    // staging lane coords
    const int svr = tid >> 4;             // row 0..15 base (+u*16)
    const int svc = (tid & 15) << 2;      // float col 0,4,..,60
    const int sh2 = (tid & 15) << 1;      // half2 unit 0,2,..,30

    // ---- load Q tiles (bias folded), half2 ----
    {
        float4 w4 = *(const float4*)&rwb[hbase + svc];
        float4 r4 = *(const float4*)&rrb[hbase + svc];
#pragma unroll
        for (int u = 0; u < 4; u++) {
            const int r = svr + u * 16;
            const size_t base = ((size_t)((MLEN + i0 + r) * BSZ + bi)) * 3072 + hbase + svc;
            float4 q4 = *(const float4*)&wh[base];
            float4 aw = make_float4(q4.x + w4.x, q4.y + w4.y, q4.z + w4.z, q4.w + w4.w);
            float4 ar2 = make_float4(q4.x + r4.x, q4.y + r4.y, q4.z + r4.z, q4.w + r4.w);
            *(uint2*)&sQw[r * 36 + sh2] = pack4(aw);
            *(uint2*)&sQr[r * 36 + sh2] = pack4(ar2);
        }
    }
    if (tid < 64) { sM[tid] = -3e38f; sL[tid] = 0.f; }

    float acc[4][4];   // PV accum frags
#pragma unroll
    for (int cb = 0; cb < 4; cb++)
#pragma unroll
        for (int q = 0; q < 4; q++) acc[cb][q] = 0.f;

    const int arow0 = (16 * rb + g) * 36;
    const int arow1 = (16 * rb + g + 8) * 36;
    const int nkt = 17 + (i0 >> 6);

    // K/V prefetch registers for tile 0
    float4 pk[4], pv[4];
#pragma unroll
    for (int u = 0; u < 4; u++) {
        const int r = svr + u * 16;
        const size_t base = ((size_t)(r * BSZ + bi)) * 3072 + hbase + svc;
        pk[u] = *(const float4*)&wh[base + 1024];
        pv[u] = *(const float4*)&wh[base + 2048];
    }

    for (int kt = 0; kt < nkt; kt++) {
        const int j0 = kt << 6;
        __syncthreads();
        // ---- store prefetched K (half2) / V (tf32); stage R (half2) ----
#pragma unroll
        for (int u = 0; u < 4; u++) {
            const int r = svr + u * 16;
            *(uint2*)&sK[r * 36 + sh2] = pack4(pk[u]);
            *(uint4*)&sV[r * 68 + svc] = cvt4(pv[u]);
        }
        const int rbase = j0 + MLEN - 1 - i0 - 63;
#pragma unroll
        for (int u = 0; u < 8; u++) {
            const int idx = tid + u * 256;
            if (idx < 2032) {
                const int r = idx >> 4, c4 = (idx & 15) << 2;
                int rg = rbase + r;
                rg = rg < 0 ? 0 : (rg > KLEN - 1 ? KLEN - 1 : rg);
                const float4 v = *(const float4*)&rh[(size_t)rg * DIM + hbase + c4];
                *(uint2*)&sR[r * 36 + ((idx & 15) << 1)] = pack4(v);
            }
        }
        __syncthreads();

        // ---- prefetch next tile's K/V (overlaps mma below) ----
        if (kt + 1 < nkt) {
#pragma unroll
            for (int u = 0; u < 4; u++) {
                const int r = svr + u * 16;
                const size_t base = ((size_t)(((j0 + 64) + r) * BSZ + bi)) * 3072 + hbase + svc;
                pk[u] = *(const float4*)&wh[base + 1024];
                pv[u] = *(const float4*)&wh[base + 2048];
            }
        }

        // ---- S and E via fp16 mma (E restricted to diagonal band blocks) ----
        float Sacc[4][4], Eacc[8][4];
#pragma unroll
        for (int cb = 0; cb < 4; cb++)
#pragma unroll
            for (int q = 0; q < 4; q++) Sacc[cb][q] = 0.f;
#pragma unroll
        for (int eb = 0; eb < 8; eb++)
#pragma unroll
            for (int q = 0; q < 4; q++) Eacc[eb][q] = 0.f;

#pragma unroll
        for (int ks = 0; ks < 4; ks++) {
            const int kb = ks * 8 + t;
            uint32_t aw[4], ar[4];
            aw[0] = sQw[arow0 + kb]; aw[1] = sQw[arow1 + kb];
            aw[2] = sQw[arow0 + kb + 4]; aw[3] = sQw[arow1 + kb + 4];
            ar[0] = sQr[arow0 + kb]; ar[1] = sQr[arow1 + kb];
            ar[2] = sQr[arow0 + kb + 4]; ar[3] = sQr[arow1 + kb + 4];
#pragma unroll
            for (int cb = 0; cb < 4; cb++) {
                const int kr = (8 * (ch * 4 + cb) + g) * 36 + kb;
                uint32_t b[2] = { sK[kr], sK[kr + 4] };
                mma_f16(Sacc[cb], aw, b);
            }
#pragma unroll
            for (int eb = 0; eb < 8; eb++) {
                if (eb >= ebmin && eb <= ebmax) {
                    const int rr = (8 * (ch * 8 + eb) + g) * 36 + kb;
                    uint32_t b[2] = { sR[rr], sR[rr + 4] };
                    mma_f16(Eacc[eb], ar, b);
                }
            }
        }
        // write S, E to smem (float2 stores)
#pragma unroll
        for (int cb = 0; cb < 4; cb++) {
            const int col = 8 * (ch * 4 + cb) + 2 * t;
            *(float2*)&sS[(16 * rb + g) * 68 + col]     = make_float2(Sacc[cb][0], Sacc[cb][1]);
            *(float2*)&sS[(16 * rb + g + 8) * 68 + col] = make_float2(Sacc[cb][2], Sacc[cb][3]);
        }
#pragma unroll
        for (int eb = 0; eb < 8; eb++) {
            if (eb >= ebmin && eb <= ebmax) {
                const int col = 8 * (ch * 8 + eb) + 2 * t;
                *(float2*)&sE[(16 * rb + g) * 136 + col]     = make_float2(Eacc[eb][0], Eacc[eb][1]);
                *(float2*)&sE[(16 * rb + g + 8) * 136 + col] = make_float2(Eacc[eb][2], Eacc[eb][3]);
            }
        }
        __syncthreads();

        // ---- online softmax: warp w owns rows w*8..w*8+7; lane quad per row ----
        {
            const int row = w * 8 + g;
            const int qi = i0 + row;
            float sarr[16];
            {
                const float4* srow = (const float4*)&sS[row * 68 + t * 16];
#pragma unroll
                for (int v4 = 0; v4 < 4; v4++) {
                    float4 s4 = srow[v4];
                    sarr[v4 * 4 + 0] = s4.x; sarr[v4 * 4 + 1] = s4.y;
                    sarr[v4 * 4 + 2] = s4.z; sarr[v4 * 4 + 3] = s4.w;
                }
            }
            const int ebase = row * 135 + t * 16 + 63;   // row*136 + (t*16 - row + 63)
            float tmax = -3e38f;
#pragma unroll
            for (int e = 0; e < 16; e++) {
                float vv = (sarr[e] + sE[ebase + e]) * 0.125f;
                if (j0 + t * 16 + e > MLEN + qi) vv = -3e38f;
                sarr[e] = vv;
                tmax = fmaxf(tmax, vv);
            }
            tmax = fmaxf(tmax, __shfl_xor_sync(0xffffffffu, tmax, 1));
            tmax = fmaxf(tmax, __shfl_xor_sync(0xffffffffu, tmax, 2));
            const float mold = sM[row];
            const float mnew = fmaxf(mold, tmax);
            float rsum = 0.f;
            uint32_t pb[16];
#pragma unroll
            for (int e = 0; e < 16; e++) {
                float p = __expf(sarr[e] - mnew);
                rsum += p;
                pb[e] = f2tf32(p);
            }
            rsum += __shfl_xor_sync(0xffffffffu, rsum, 1);
            rsum += __shfl_xor_sync(0xffffffffu, rsum, 2);
            if (t == 0) {
                const float al = __expf(mold - mnew);
                sM[row] = mnew;
                sA[row] = al;
                sL[row] = sL[row] * al + rsum;
            }
            uint4* pd = (uint4*)&sP[row * 68 + t * 16];
            pd[0] = make_uint4(pb[0], pb[1], pb[2], pb[3]);
            pd[1] = make_uint4(pb[4], pb[5], pb[6], pb[7]);
            pd[2] = make_uint4(pb[8], pb[9], pb[10], pb[11]);
            pd[3] = make_uint4(pb[12], pb[13], pb[14], pb[15]);
        }
        __syncthreads();

        // ---- rescale + P@V via tf32 mma ----
        {
            const float al0 = sA[16 * rb + g];
            const float al1 = sA[16 * rb + g + 8];
#pragma unroll
            for (int cb = 0; cb < 4; cb++) {
                acc[cb][0] *= al0; acc[cb][1] *= al0;
                acc[cb][2] *= al1; acc[cb][3] *= al1;
            }
            const int prow0 = (16 * rb + g) * 68;
            const int prow1 = (16 * rb + g + 8) * 68;
#pragma unroll
            for (int ks = 0; ks < 8; ks++) {
                const int kc = ks * 8 + t;
                uint32_t a[4] = { sP[prow0 + kc], sP[prow1 + kc],
                                  sP[prow0 + kc + 4], sP[prow1 + kc + 4] };
#pragma unroll
                for (int cb = 0; cb < 4; cb++) {
                    const int col = 8 * (ch * 4 + cb) + g;
                    uint32_t b[2] = { sV[(ks * 8 + t) * 68 + col],
                                      sV[(ks * 8 + t + 4) * 68 + col] };
                    mma_tf32(acc[cb], a, b);
                }
            }
        }
    }

    // ---- finalize ----
    const float linv0 = 1.f / sL[16 * rb + g];
    const float linv1 = 1.f / sL[16 * rb + g + 8];
    const int r0 = i0 + 16 * rb + g;
#pragma unroll
    for (int cb = 0; cb < 4; cb++) {
        const int col = hbase + 8 * (ch * 4 + cb) + 2 * t;
        float2 o0, o1;
        o0.x = acc[cb][0] * linv0; o0.y = acc[cb][1] * linv0;
        o1.x = acc[cb][2] * linv1; o1.y = acc[cb][3] * linv1;
        *(float2*)&av[((size_t)(r0 * BSZ + bi)) * DIM + col] = o0;
        *(float2*)&av[((size_t)((r0 + 8) * BSZ + bi)) * DIM + col] = o1;
    }
}

// ---------------- residual + layernorm (row per block) ----------------
__global__ __launch_bounds__(256) void ln_kernel(
    const float* __restrict__ x, const float* __restrict__ res,
    const float* __restrict__ g, const float* __restrict__ b,
    float* __restrict__ out1, float* __restrict__ out2)
{
    const int row = blockIdx.x;
    const int tid = threadIdx.x;
    float4 xv = *(const float4*)(x + (size_t)row * DIM + tid * 4);
    float4 rv = *(const float4*)(res + (size_t)row * DIM + tid * 4);
    float v0 = xv.x + rv.x, v1 = xv.y + rv.y, v2 = xv.z + rv.z, v3 = xv.w + rv.w;
    float s = v0 + v1 + v2 + v3;
    float q = v0 * v0 + v1 * v1 + v2 * v2 + v3 * v3;
#pragma unroll
    for (int off = 16; off > 0; off >>= 1) {
        s += __shfl_xor_sync(0xffffffffu, s, off);
        q += __shfl_xor_sync(0xffffffffu, q, off);
    }
    __shared__ float sb[8], qb[8];
    const int w = tid >> 5, lane = tid & 31;
    if (lane == 0) { sb[w] = s; qb[w] = q; }
    __syncthreads();
    if (w == 0) {
        float s2 = (lane < 8) ? sb[lane] : 0.f;
        float q2 = (lane < 8) ? qb[lane] : 0.f;
#pragma unroll
        for (int off = 4; off > 0; off >>= 1) {
            s2 += __shfl_xor_sync(0xffffffffu, s2, off);
            q2 += __shfl_xor_sync(0xffffffffu, q2, off);
        }
        if (lane == 0) { sb[0] = s2; qb[0] = q2; }
    }
    __syncthreads();
    const float mean = sb[0] * (1.0f / DIM);
    const float var  = qb[0] * (1.0f / DIM) - mean * mean;
    const float rstd = rsqrtf(var + 1e-5f);
    float4 gv = *(const float4*)(g + tid * 4);
    float4 bv = *(const float4*)(b + tid * 4);
    float4 o;
    o.x = (v0 - mean) * rstd * gv.x + bv.x;
    o.y = (v1 - mean) * rstd * gv.y + bv.y;
    o.z = (v2 - mean) * rstd * gv.z + bv.z;
    o.w = (v3 - mean) * rstd * gv.w + bv.w;
    *(float4*)(out1 + (size_t)row * DIM + tid * 4) = o;
    if (out2) *(float4*)(out2 + (size_t)row * DIM + tid * 4) = o;
}

// ---------------- host orchestration ----------------
extern "C" void kernel_launch(void* const* d_in, const int* in_sizes, int n_in,
                              void* d_out, int out_size) {
    const float* mems = (const float*)d_in[0];
    const float* raw  = (const float*)d_in[1];
    /* d_in[2] = attention_mask: analytic, ignored */
    const float* rwb  = (const float*)d_in[3];
    const float* rrb  = (const float*)d_in[4];
    const float* qkvw = (const float*)d_in[5];
    const float* rw   = (const float*)d_in[6];
    const float* ow   = (const float*)d_in[7];
    const float* ln1g = (const float*)d_in[8];
    const float* ln1b = (const float*)d_in[9];
    const float* fw1  = (const float*)d_in[10];
    const float* fb1  = (const float*)d_in[11];
    const float* fw2  = (const float*)d_in[12];
    const float* fb2  = (const float*)d_in[13];
    const float* ln2g = (const float*)d_in[14];
    const float* ln2b = (const float*)d_in[15];
    float* out = (float*)d_out;

    const bool full_out = out_size >= (NLAY + 2) * NE;   // core + new_mems(5 slabs)
    float* out_mems = full_out ? out + NE : nullptr;

    float *wh, *pos, *rh, *av, *tmp, *core, *core2, *ff;
    cudaGetSymbolAddress((void**)&wh,   g_wheads);
    cudaGetSymbolAddress((void**)&pos,  g_pos);
    cudaGetSymbolAddress((void**)&rh,   g_rhead);
    cudaGetSymbolAddress((void**)&av,   g_attnvec);
    cudaGetSymbolAddress((void**)&tmp,  g_tmp);
    cudaGetSymbolAddress((void**)&core, g_core);
    cudaGetSymbolAddress((void**)&core2,g_core2);
    cudaGetSymbolAddress((void**)&ff,   g_ff);

    cudaFuncSetAttribute((const void*)attn_mma_kernel,
                         cudaFuncAttributeMaxDynamicSharedMemorySize, ATTN2_SMEM_BYTES);

    const int C4 = NE / 4;               // float4 count per slab
    const int CB = (C4 + 255) / 256;

    copy_kernel<<<CB, 256>>>(core, raw, C4);
    if (out_mems) copy_kernel<<<CB, 256>>>(out_mems, raw, C4);
    pos_kernel<<<(KLEN * DIM + 255) / 256, 256>>>(pos);

    for (int i = 0; i < NLAY; i++) {
        // QKV split, reading sources directly (no cat buffer):
        //  - mem rows (from mems[i]) need only K,V (cols 1024..3071)
        //  - q rows (from core) need all 3072 cols
        mma_gemm<<<dim3(16, 16), 256>>>(
            mems + (size_t)i * NE, qkvw + (size_t)i * DIM * 3 * DIM + 1024, wh + 1024,
            2048, 2048, 1024, 1024, 3072, 3072, nullptr, 0);
        mma_gemm<<<dim3(24, 16), 256>>>(
            core, qkvw + (size_t)i * DIM * 3 * DIM,
            wh + (size_t)2048 * 3072,
            2048, 3072, 1024, 1024, 3072, 3072, nullptr, 0);
        mma_gemm<<<dim3(8, 16), 256>>>(
            pos, rw + (size_t)i * DIM * DIM, rh,
            2048, 1024, 1024, 1024, 1024, 1024, nullptr, 0);

        attn_mma_kernel<<<dim3(16, 32), 256, ATTN2_SMEM_BYTES>>>(wh, rh, rwb, rrb, av);

        mma_gemm<<<dim3(8, 16), 256>>>(
            av, ow + (size_t)i * DIM * DIM, tmp,
            2048, 1024, 1024, 1024, 1024, 1024, nullptr, 0);
        ln_kernel<<<2048, 256>>>(tmp, core, ln1g + i * DIM, ln1b + i * DIM, core2, nullptr);

        mma_gemm<<<dim3(8, 16), 256>>>(
            core2, fw1 + (size_t)i * DIM * DIM, ff,
            2048, 1024, 1024, 1024, 1024, 1024, fb1 + i * DIM, 1);
        mma_gemm<<<dim3(8, 16), 256>>>(
            ff, fw2 + (size_t)i * DIM * DIM, tmp,
            2048, 1024, 1024, 1024, 1024, 1024, fb2 + i * DIM, 0);
        float* lnDst = (i == NLAY - 1) ? out : core;
        ln_kernel<<<2048, 256>>>(tmp, core2, ln2g + i * DIM, ln2b + i * DIM, lnDst,
                                 out_mems ? out_mems + (size_t)(i + 1) * NE : nullptr);
    }
}

// round 15
// speedup vs baseline: 1.4896x; 1.0128x over previous
#include <cuda_runtime.h>
#include <cuda_fp16.h>
#include <math.h>
#include <stdint.h>

#define L_Q   1024
#define BSZ   2
#define DIM   1024
#define NHEAD 16
#define DHEAD 64
#define NLAY  4
#define MLEN  1024
#define KLEN  2048
#define NE    (L_Q*BSZ*DIM)   /* 2097152 floats per (L,B,D) slab */
#define WHS   ((size_t)KLEN*BSZ*3*DIM)   /* wheads slab per layer */
#define RHS   ((size_t)KLEN*DIM)         /* rhead slab per layer */

// ---------------- scratch (device globals; no allocation allowed) ----------------
__device__ float g_wheads[NLAY * WHS];   // 201 MB (per-layer)
__device__ float g_pos[(size_t)KLEN*DIM];
__device__ float g_rhead[NLAY * RHS];    // 33.5 MB (per-layer)
__device__ float g_attnvec[NE];
__device__ float g_tmp[NE];
__device__ float g_core[NE];
__device__ float g_core2[NE];
__device__ float g_ff[NE];

// ---------------- simple float4 copy ----------------
__global__ void copy_kernel(float* __restrict__ dst, const float* __restrict__ src, int n4) {
    int i = blockIdx.x * blockDim.x + threadIdx.x;
    if (i < n4) ((float4*)dst)[i] = ((const float4*)src)[i];
}

// ---------------- positional embedding ----------------
__global__ void pos_kernel(float* __restrict__ pos) {
    int idx = blockIdx.x * blockDim.x + threadIdx.x;
    if (idx >= KLEN * DIM) return;
    int j = idx >> 10;
    int i = idx & 1023;
    int t = i & 511;
    float x = (float)(2 * t) * (1.0f / 1024.0f);
    float invf = expf(-x * 9.210340371976184f);
    float arg = (float)(KLEN - 1 - j) * invf;
    pos[idx] = (i < 512) ? sinf(arg) : cosf(arg);
}

// ---------------- helpers ----------------
__device__ __forceinline__ uint32_t f2tf32(float f) {
    uint32_t u;
    asm("cvt.rna.tf32.f32 %0, %1;" : "=r"(u) : "f"(f));
    return u;
}
__device__ __forceinline__ uint4 cvt4(float4 v) {
    return make_uint4(f2tf32(v.x), f2tf32(v.y), f2tf32(v.z), f2tf32(v.w));
}
__device__ __forceinline__ void mma_tf32(float* c, const uint32_t* a, const uint32_t* b) {
    asm volatile(
        "mma.sync.aligned.m16n8k8.row.col.f32.tf32.tf32.f32 "
        "{%0,%1,%2,%3}, {%4,%5,%6,%7}, {%8,%9}, {%0,%1,%2,%3};"
        : "+f"(c[0]), "+f"(c[1]), "+f"(c[2]), "+f"(c[3])
        : "r"(a[0]), "r"(a[1]), "r"(a[2]), "r"(a[3]), "r"(b[0]), "r"(b[1]));
}
__device__ __forceinline__ uint32_t pack_h2(float lo, float hi) {
    uint32_t r;
    asm("cvt.rn.f16x2.f32 %0, %1, %2;" : "=r"(r) : "f"(hi), "f"(lo));
    return r;
}
__device__ __forceinline__ uint2 pack4(float4 v) {
    return make_uint2(pack_h2(v.x, v.y), pack_h2(v.z, v.w));
}
__device__ __forceinline__ void mma_f16(float* c, const uint32_t* a, const uint32_t* b) {
    asm volatile(
        "mma.sync.aligned.m16n8k16.row.col.f32.f16.f16.f32 "
        "{%0,%1,%2,%3}, {%4,%5,%6,%7}, {%8,%9}, {%0,%1,%2,%3};"
        : "+f"(c[0]), "+f"(c[1]), "+f"(c[2]), "+f"(c[3])
        : "r"(a[0]), "r"(a[1]), "r"(a[2]), "r"(a[3]), "r"(b[0]), "r"(b[1]));
}

// ---------------- fp16 GEMM body (device function) ----------------
// A[M,K] lda, B[K,N] ldb, C[M,N] ldc (fp32). fp16 operands, fp32 accum.
struct GemmSmem {
    uint32_t As[2][2048];
    uint32_t Bs[2][2048];
};

__device__ __forceinline__ void gemm_block(
    GemmSmem* sm,
    const float* __restrict__ A, const float* __restrict__ B, float* __restrict__ C,
    int K, int lda, int ldb, int ldc,
    const float* __restrict__ bias, int relu, int bx, int by)
{
    uint32_t (*As)[2048] = sm->As;
    uint32_t (*Bs)[2048] = sm->Bs;

    const int tid = threadIdx.x;
    const int lane = tid & 31;
    const int w = tid >> 5;
    const int wr = w & 1;
    const int wc = w >> 1;

    const int ar  = tid >> 1;
    const int kh  = tid & 1;
    const int ac  = ((ar >> 1) & 3) + 4 * kh;
    const int abase = (((kh * 8 + (ar >> 4)) * 32 + (ar & 7) * 4) << 2) + ((ar >> 3) & 1);
    const float* Ag = A + (size_t)(by * 128 + ar) * lda + kh * 16;

    const int bl   = lane;
    const int bnn  = bl >> 2;
    const int bppl = bl & 3;
    const int blh  = (bl >> 4) & 1;
    const int nb0  = (tid >> 5) << 1;
    const int bcol0 = bx * 128;

    float acc[4][4][4];
#pragma unroll
    for (int mi = 0; mi < 4; mi++)
#pragma unroll
        for (int ni = 0; ni < 4; ni++)
#pragma unroll
            for (int q = 0; q < 4; q++) acc[mi][ni][q] = 0.f;

    uint32_t paH[8];
    uint32_t pbH[8];

#pragma unroll
    for (int tt = 0; tt < 4; tt++) {
        const float4 v = *(const float4*)(Ag + tt * 4);
        paH[tt * 2 + 0] = pack_h2(v.x, v.y);
        paH[tt * 2 + 1] = pack_h2(v.z, v.w);
    }
#pragma unroll
    for (int j = 0; j < 4; j++) {
        const int ppq4 = (j + blh) & 3;
        const int p = ppq4 * 4 + bppl;
#pragma unroll
        for (int nbi = 0; nbi < 2; nbi++) {
            const int n = (nb0 + nbi) * 8 + bnn;
            pbH[j * 2 + nbi] = pack_h2(B[(size_t)(2 * p) * ldb + bcol0 + n],
                                       B[(size_t)(2 * p + 1) * ldb + bcol0 + n]);
        }
    }
#pragma unroll
    for (int j = 0; j < 8; j++) {
        const int pp2 = (j + ac) & 7;
        As[0][abase + ((pp2 & 3) << 2) + ((pp2 >> 2) << 1)] = paH[pp2];
    }
#pragma unroll
    for (int j = 0; j < 4; j++) {
        const int ppq4 = (j + blh) & 3;
        const int ks = ppq4 >> 1, q = ppq4 & 1;
#pragma unroll
        for (int nbi = 0; nbi < 2; nbi++) {
            const int nb = nb0 + nbi;
            Bs[0][(((ks * 16 + nb) * 32 + bl) << 1) + q] = pbH[j * 2 + nbi];
        }
    }
    __syncthreads();

    const int NT = K >> 5;
    for (int T = 0; T < NT; T++) {
        const int buf = T & 1;
        if (T + 1 < NT) {
            const int off = (T + 1) << 5;
#pragma unroll
            for (int tt = 0; tt < 4; tt++) {
                const float4 v = *(const float4*)(Ag + off + tt * 4);
                paH[tt * 2 + 0] = pack_h2(v.x, v.y);
                paH[tt * 2 + 1] = pack_h2(v.z, v.w);
            }
#pragma unroll
            for (int j = 0; j < 4; j++) {
                const int ppq4 = (j + blh) & 3;
                const int p = ppq4 * 4 + bppl;
#pragma unroll
                for (int nbi = 0; nbi < 2; nbi++) {
                    const int n = (nb0 + nbi) * 8 + bnn;
                    pbH[j * 2 + nbi] = pack_h2(B[(size_t)(off + 2 * p) * ldb + bcol0 + n],
                                               B[(size_t)(off + 2 * p + 1) * ldb + bcol0 + n]);
                }
            }
        }
#pragma unroll
        for (int ks = 0; ks < 2; ks++) {
            uint32_t afr[4][4], bfr[4][2];
#pragma unroll
            for (int mi = 0; mi < 4; mi++) {
                const uint4 v = *(const uint4*)&As[buf][(((ks * 8 + wr * 4 + mi) * 32 + lane) << 2)];
                afr[mi][0] = v.x; afr[mi][1] = v.y; afr[mi][2] = v.z; afr[mi][3] = v.w;
            }
#pragma unroll
            for (int ni = 0; ni < 4; ni++) {
                const uint2 v = *(const uint2*)&Bs[buf][(((ks * 16 + wc * 4 + ni) * 32 + lane) << 1)];
                bfr[ni][0] = v.x; bfr[ni][1] = v.y;
            }
#pragma unroll
            for (int mi = 0; mi < 4; mi++)
#pragma unroll
                for (int ni = 0; ni < 4; ni++)
                    mma_f16(acc[mi][ni], afr[mi], bfr[ni]);
        }
        if (T + 1 < NT) {
            const int nb2 = buf ^ 1;
#pragma unroll
            for (int j = 0; j < 8; j++) {
                const int pp2 = (j + ac) & 7;
                As[nb2][abase + ((pp2 & 3) << 2) + ((pp2 >> 2) << 1)] = paH[pp2];
            }
#pragma unroll
            for (int j = 0; j < 4; j++) {
                const int ppq4 = (j + blh) & 3;
                const int ks = ppq4 >> 1, q = ppq4 & 1;
#pragma unroll
                for (int nbi = 0; nbi < 2; nbi++) {
                    const int nb = nb0 + nbi;
                    Bs[nb2][(((ks * 16 + nb) * 32 + bl) << 1) + q] = pbH[j * 2 + nbi];
                }
            }
        }
        __syncthreads();
    }

    const int g = lane >> 2;
    const int t = lane & 3;
#pragma unroll
    for (int mi = 0; mi < 4; mi++) {
        const int r0 = by * 128 + wr * 64 + mi * 16 + g;
#pragma unroll
        for (int ni = 0; ni < 4; ni++) {
            const int c0 = bx * 128 + wc * 32 + ni * 8 + t * 2;
            float b0 = 0.f, b1 = 0.f;
            if (bias) { b0 = bias[c0]; b1 = bias[c0 + 1]; }
            float2 o0, o1;
            o0.x = acc[mi][ni][0] + b0; o0.y = acc[mi][ni][1] + b1;
            o1.x = acc[mi][ni][2] + b0; o1.y = acc[mi][ni][3] + b1;
            if (relu) {
                o0.x = fmaxf(o0.x, 0.f); o0.y = fmaxf(o0.y, 0.f);
                o1.x = fmaxf(o1.x, 0.f); o1.y = fmaxf(o1.y, 0.f);
            }
            *(float2*)&C[(size_t)r0 * ldc + c0] = o0;
            *(float2*)&C[(size_t)(r0 + 8) * ldc + c0] = o1;
        }
    }
}

// standalone GEMM
__global__ __launch_bounds__(256, 2) void mma_gemm(
    const float* __restrict__ A, const float* __restrict__ B, float* __restrict__ C,
    int K, int lda, int ldb, int ldc,
    const float* __restrict__ bias, int relu)
{
    __shared__ __align__(16) GemmSmem sm;
    gemm_block(&sm, A, B, C, K, lda, ldb, ldc, bias, relu, blockIdx.x, blockIdx.y);
}

// batched upfront launch: all layers' K/V projections + pos GEMMs.
// grid (96, 16): bx<64 -> KV GEMM (layer bx>>4, tile bx&15); else pos (layer (bx-64)>>3, tile &7)
__global__ __launch_bounds__(256, 2) void batch_pre_kernel(
    const float* __restrict__ mems, const float* __restrict__ qkvw,
    const float* __restrict__ pos,  const float* __restrict__ rw,
    float* __restrict__ wh, float* __restrict__ rh)
{
    __shared__ __align__(16) GemmSmem sm;
    const int bx = blockIdx.x, by = blockIdx.y;
    if (bx < 64) {
        const int lay = bx >> 4, bxl = bx & 15;
        gemm_block(&sm,
                   mems + (size_t)lay * NE,
                   qkvw + (size_t)lay * DIM * 3 * DIM + 1024,
                   wh + lay * WHS + 1024,
                   1024, 1024, 3072, 3072, nullptr, 0, bxl, by);
    } else {
        const int b2 = bx - 64;
        const int lay = b2 >> 3, bxl = b2 & 7;
        gemm_block(&sm,
                   pos,
                   rw + (size_t)lay * DIM * DIM,
                   rh + lay * RHS,
                   1024, 1024, 1024, 1024, nullptr, 0, bxl, by);
    }
}

// ---------------- tensor-core fused rel-attention ----------------
// fp16 S/E (pitch-36 half2), tf32 PV (pitch-68), E-band skip, R double-buffer.
#define AT_QW 0                     /* 64x36 half2 */
#define AT_QR 2304
#define AT_K  4608
#define AT_R  6912                  /* 2 x 128x36 half2 */
#define AT_V  16128                 /* 64x68 tf32 */
#define AT_S  20480                 /* 64x68 f32 */
#define AT_E  24832                 /* 64x136 f32 */
#define AT_P  33536                 /* 64x68 tf32 */
#define AT_M  37888
#define AT_L  37952
#define AT_A  38016
#define ATTN2_SMEM_FLOATS 38080
#define ATTN2_SMEM_BYTES  (ATTN2_SMEM_FLOATS * 4)

__global__ __launch_bounds__(256) void attn_mma_kernel(
    const float* __restrict__ wh, const float* __restrict__ rh,
    const float* __restrict__ rwb, const float* __restrict__ rrb,
    float* __restrict__ av)
{
    extern __shared__ float smf[];
    uint32_t* sQw = (uint32_t*)(smf + AT_QW);
    uint32_t* sQr = (uint32_t*)(smf + AT_QR);
    uint32_t* sK  = (uint32_t*)(smf + AT_K);
    uint32_t* sR0 = (uint32_t*)(smf + AT_R);
    uint32_t* sR1 = sR0 + 4608;
    uint32_t* sV  = (uint32_t*)(smf + AT_V);
    float*    sS  = smf + AT_S;
    float*    sE  = smf + AT_E;
    uint32_t* sP  = (uint32_t*)(smf + AT_P);
    float*    sM  = smf + AT_M;
    float*    sL  = smf + AT_L;
    float*    sA  = smf + AT_A;

    const int i0 = (15 - blockIdx.x) << 6;
    const int bi = blockIdx.y >> 4;
    const int hn = blockIdx.y & 15;
    const int tid = threadIdx.x;
    const int lane = tid & 31;
    const int w = tid >> 5;
    const int rb = w >> 1;
    const int ch = w & 1;
    const int g = lane >> 2;
    const int t = lane & 3;
    const int hbase = hn << 6;

    int ebmin = 41 - 16 * rb - 64 * ch;
    ebmin = ebmin <= 0 ? 0 : ((ebmin + 7) >> 3);
    int ebmax = (126 - 16 * rb - 64 * ch) >> 3;
    if (ebmax > 7) ebmax = 7;

    const int svr = tid >> 4;
    const int svc = (tid & 15) << 2;
    const int sh2 = (tid & 15) << 1;

    {
        float4 w4 = *(const float4*)&rwb[hbase + svc];
        float4 r4 = *(const float4*)&rrb[hbase + svc];
#pragma unroll
        for (int u = 0; u < 4; u++) {
            const int r = svr + u * 16;
            const size_t base = ((size_t)((MLEN + i0 + r) * BSZ + bi)) * 3072 + hbase + svc;
            float4 q4 = *(const float4*)&wh[base];
            float4 aw = make_float4(q4.x + w4.x, q4.y + w4.y, q4.z + w4.z, q4.w + w4.w);
            float4 ar2 = make_float4(q4.x + r4.x, q4.y + r4.y, q4.z + r4.z, q4.w + r4.w);
            *(uint2*)&sQw[r * 36 + sh2] = pack4(aw);
            *(uint2*)&sQr[r * 36 + sh2] = pack4(ar2);
        }
    }
    if (tid < 64) { sM[tid] = -3e38f; sL[tid] = 0.f; }

    float acc[4][4];
#pragma unroll
    for (int cb = 0; cb < 4; cb++)
#pragma unroll
        for (int q = 0; q < 4; q++) acc[cb][q] = 0.f;

    const int arow0 = (16 * rb + g) * 36;
    const int arow1 = (16 * rb + g + 8) * 36;
    const int nkt = 17 + (i0 >> 6);
    const int C0 = MLEN - 1 - i0 - 63;   // rbase(kt) = 64*kt + C0

    float4 pk[4], pv[4], pr[4];
#pragma unroll
    for (int u = 0; u < 4; u++) {
        const int r = svr + u * 16;
        const size_t base = ((size_t)(r * BSZ + bi)) * 3072 + hbase + svc;
        pk[u] = *(const float4*)&wh[base + 1024];
        pv[u] = *(const float4*)&wh[base + 2048];
    }

    for (int kt = 0; kt < nkt; kt++) {
        const int j0 = kt << 6;
        uint32_t* sRn = (kt & 1) ? sR1 : sR0;
        uint32_t* sRo = (kt & 1) ? sR0 : sR1;
        __syncthreads();
        // ---- staging: K/V from prefetch regs; R new-buffer fill ----
#pragma unroll
        for (int u = 0; u < 4; u++) {
            const int r = svr + u * 16;
            *(uint2*)&sK[r * 36 + sh2] = pack4(pk[u]);
            *(uint4*)&sV[r * 68 + svc] = cvt4(pv[u]);
        }
        if (kt == 0) {
            const int rbase = C0;
#pragma unroll
            for (int u = 0; u < 8; u++) {
                const int idx = tid + u * 256;
                if (idx < 2032) {
                    const int r = idx >> 4, c4 = (idx & 15) << 2;
                    int rg = rbase + r;
                    rg = rg < 0 ? 0 : (rg > KLEN - 1 ? KLEN - 1 : rg);
                    const float4 v = *(const float4*)&rh[(size_t)rg * DIM + hbase + c4];
                    *(uint2*)&sRn[r * 36 + ((idx & 15) << 1)] = pack4(v);
                }
            }
        } else {
            // copy rows 0..62 from old buffer rows 64..126
#pragma unroll
            for (int u = 0; u < 3; u++) {
                const int idx = tid + u * 256;
                if (idx < 567) {
                    const int r = idx / 9, q4 = idx - r * 9;
                    *(uint4*)&sRn[r * 36 + q4 * 4] = *(const uint4*)&sRo[(r + 64) * 36 + q4 * 4];
                }
            }
            // store prefetched new rows 63..126
#pragma unroll
            for (int u = 0; u < 4; u++) {
                const int idx = tid + u * 256;
                const int r = 63 + (idx >> 4);
                *(uint2*)&sRn[r * 36 + ((idx & 15) << 1)] = pack4(pr[u]);
            }
        }
        __syncthreads();

        // ---- prefetch next tile's K/V and R-new rows (overlaps mma) ----
        if (kt + 1 < nkt) {
#pragma unroll
            for (int u = 0; u < 4; u++) {
                const int r = svr + u * 16;
                const size_t base = ((size_t)(((j0 + 64) + r) * BSZ + bi)) * 3072 + hbase + svc;
                pk[u] = *(const float4*)&wh[base + 1024];
                pv[u] = *(const float4*)&wh[base + 2048];
            }
            const int rbn = 64 * (kt + 1) + C0;
#pragma unroll
            for (int u = 0; u < 4; u++) {
                const int idx = tid + u * 256;
                int rg = rbn + 63 + (idx >> 4);
                rg = rg < 0 ? 0 : (rg > KLEN - 1 ? KLEN - 1 : rg);
                pr[u] = *(const float4*)&rh[(size_t)rg * DIM + hbase + ((idx & 15) << 2)];
            }
        }

        // ---- S and E via fp16 mma ----
        float Sacc[4][4], Eacc[8][4];
#pragma unroll
        for (int cb = 0; cb < 4; cb++)
#pragma unroll
            for (int q = 0; q < 4; q++) Sacc[cb][q] = 0.f;
#pragma unroll
        for (int eb = 0; eb < 8; eb++)
#pragma unroll
            for (int q = 0; q < 4; q++) Eacc[eb][q] = 0.f;

#pragma unroll
        for (int ks = 0; ks < 4; ks++) {
            const int kb = ks * 8 + t;
            uint32_t aw[4], ar[4];
            aw[0] = sQw[arow0 + kb]; aw[1] = sQw[arow1 + kb];
            aw[2] = sQw[arow0 + kb + 4]; aw[3] = sQw[arow1 + kb + 4];
            ar[0] = sQr[arow0 + kb]; ar[1] = sQr[arow1 + kb];
            ar[2] = sQr[arow0 + kb + 4]; ar[3] = sQr[arow1 + kb + 4];
#pragma unroll
            for (int cb = 0; cb < 4; cb++) {
                const int kr = (8 * (ch * 4 + cb) + g) * 36 + kb;
                uint32_t b[2] = { sK[kr], sK[kr + 4] };
                mma_f16(Sacc[cb], aw, b);
            }
#pragma unroll
            for (int eb = 0; eb < 8; eb++) {
                if (eb >= ebmin && eb <= ebmax) {
                    const int rr = (8 * (ch * 8 + eb) + g) * 36 + kb;
                    uint32_t b[2] = { sRn[rr], sRn[rr + 4] };
                    mma_f16(Eacc[eb], ar, b);
                }
            }
        }
#pragma unroll
        for (int cb = 0; cb < 4; cb++) {
            const int col = 8 * (ch * 4 + cb) + 2 * t;
            *(float2*)&sS[(16 * rb + g) * 68 + col]     = make_float2(Sacc[cb][0], Sacc[cb][1]);
            *(float2*)&sS[(16 * rb + g + 8) * 68 + col] = make_float2(Sacc[cb][2], Sacc[cb][3]);
        }
#pragma unroll
        for (int eb = 0; eb < 8; eb++) {
            if (eb >= ebmin && eb <= ebmax) {
                const int col = 8 * (ch * 8 + eb) + 2 * t;
                *(float2*)&sE[(16 * rb + g) * 136 + col]     = make_float2(Eacc[eb][0], Eacc[eb][1]);
                *(float2*)&sE[(16 * rb + g + 8) * 136 + col] = make_float2(Eacc[eb][2], Eacc[eb][3]);
            }
        }
        __syncthreads();

        // ---- online softmax ----
        {
            const int row = w * 8 + g;
            const int qi = i0 + row;
            float sarr[16];
            {
                const float4* srow = (const float4*)&sS[row * 68 + t * 16];
#pragma unroll
                for (int v4 = 0; v4 < 4; v4++) {
                    float4 s4 = srow[v4];
                    sarr[v4 * 4 + 0] = s4.x; sarr[v4 * 4 + 1] = s4.y;
                    sarr[v4 * 4 + 2] = s4.z; sarr[v4 * 4 + 3] = s4.w;
                }
            }
            const int ebase = row * 135 + t * 16 + 63;
            float tmax = -3e38f;
#pragma unroll
            for (int e = 0; e < 16; e++) {
                float vv = (sarr[e] + sE[ebase + e]) * 0.125f;
                if (j0 + t * 16 + e > MLEN + qi) vv = -3e38f;
                sarr[e] = vv;
                tmax = fmaxf(tmax, vv);
            }
            tmax = fmaxf(tmax, __shfl_xor_sync(0xffffffffu, tmax, 1));
            tmax = fmaxf(tmax, __shfl_xor_sync(0xffffffffu, tmax, 2));
            const float mold = sM[row];
            const float mnew = fmaxf(mold, tmax);
            float rsum = 0.f;
            uint32_t pb[16];
#pragma unroll
            for (int e = 0; e < 16; e++) {
                float p = __expf(sarr[e] - mnew);
                rsum += p;
                pb[e] = f2tf32(p);
            }
            rsum += __shfl_xor_sync(0xffffffffu, rsum, 1);
            rsum += __shfl_xor_sync(0xffffffffu, rsum, 2);
            if (t == 0) {
                const float al = __expf(mold - mnew);
                sM[row] = mnew;
                sA[row] = al;
                sL[row] = sL[row] * al + rsum;
            }
            uint4* pd = (uint4*)&sP[row * 68 + t * 16];
            pd[0] = make_uint4(pb[0], pb[1], pb[2], pb[3]);
            pd[1] = make_uint4(pb[4], pb[5], pb[6], pb[7]);
            pd[2] = make_uint4(pb[8], pb[9], pb[10], pb[11]);
            pd[3] = make_uint4(pb[12], pb[13], pb[14], pb[15]);
        }
        __syncthreads();

        // ---- rescale + P@V via tf32 mma ----
        {
            const float al0 = sA[16 * rb + g];
            const float al1 = sA[16 * rb + g + 8];
#pragma unroll
            for (int cb = 0; cb < 4; cb++) {
                acc[cb][0] *= al0; acc[cb][1] *= al0;
                acc[cb][2] *= al1; acc[cb][3] *= al1;
            }
            const int prow0 = (16 * rb + g) * 68;
            const int prow1 = (16 * rb + g + 8) * 68;
#pragma unroll
            for (int ks = 0; ks < 8; ks++) {
                const int kc = ks * 8 + t;
                uint32_t a[4] = { sP[prow0 + kc], sP[prow1 + kc],
                                  sP[prow0 + kc + 4], sP[prow1 + kc + 4] };
#pragma unroll
                for (int cb = 0; cb < 4; cb++) {
                    const int col = 8 * (ch * 4 + cb) + g;
                    uint32_t b[2] = { sV[(ks * 8 + t) * 68 + col],
                                      sV[(ks * 8 + t + 4) * 68 + col] };
                    mma_tf32(acc[cb], a, b);
                }
            }
        }
    }

    // ---- finalize ----
    const float linv0 = 1.f / sL[16 * rb + g];
    const float linv1 = 1.f / sL[16 * rb + g + 8];
    const int r0 = i0 + 16 * rb + g;
#pragma unroll
    for (int cb = 0; cb < 4; cb++) {
        const int col = hbase + 8 * (ch * 4 + cb) + 2 * t;
        float2 o0, o1;
        o0.x = acc[cb][0] * linv0; o0.y = acc[cb][1] * linv0;
        o1.x = acc[cb][2] * linv1; o1.y = acc[cb][3] * linv1;
        *(float2*)&av[((size_t)(r0 * BSZ + bi)) * DIM + col] = o0;
        *(float2*)&av[((size_t)((r0 + 8) * BSZ + bi)) * DIM + col] = o1;
    }
}

// ---------------- residual + layernorm (row per block) ----------------
__global__ __launch_bounds__(256) void ln_kernel(
    const float* __restrict__ x, const float* __restrict__ res,
    const float* __restrict__ g, const float* __restrict__ b,
    float* __restrict__ out1, float* __restrict__ out2)
{
    const int row = blockIdx.x;
    const int tid = threadIdx.x;
    float4 xv = *(const float4*)(x + (size_t)row * DIM + tid * 4);
    float4 rv = *(const float4*)(res + (size_t)row * DIM + tid * 4);
    float v0 = xv.x + rv.x, v1 = xv.y + rv.y, v2 = xv.z + rv.z, v3 = xv.w + rv.w;
    float s = v0 + v1 + v2 + v3;
    float q = v0 * v0 + v1 * v1 + v2 * v2 + v3 * v3;
#pragma unroll
    for (int off = 16; off > 0; off >>= 1) {
        s += __shfl_xor_sync(0xffffffffu, s, off);
        q += __shfl_xor_sync(0xffffffffu, q, off);
    }
    __shared__ float sb[8], qb[8];
    const int w = tid >> 5, lane = tid & 31;
    if (lane == 0) { sb[w] = s; qb[w] = q; }
    __syncthreads();
    if (w == 0) {
        float s2 = (lane < 8) ? sb[lane] : 0.f;
        float q2 = (lane < 8) ? qb[lane] : 0.f;
#pragma unroll
        for (int off = 4; off > 0; off >>= 1) {
            s2 += __shfl_xor_sync(0xffffffffu, s2, off);
            q2 += __shfl_xor_sync(0xffffffffu, q2, off);
        }
        if (lane == 0) { sb[0] = s2; qb[0] = q2; }
    }
    __syncthreads();
    const float mean = sb[0] * (1.0f / DIM);
    const float var  = qb[0] * (1.0f / DIM) - mean * mean;
    const float rstd = rsqrtf(var + 1e-5f);
    float4 gv = *(const float4*)(g + tid * 4);
    float4 bv = *(const float4*)(b + tid * 4);
    float4 o;
    o.x = (v0 - mean) * rstd * gv.x + bv.x;
    o.y = (v1 - mean) * rstd * gv.y + bv.y;
    o.z = (v2 - mean) * rstd * gv.z + bv.z;
    o.w = (v3 - mean) * rstd * gv.w + bv.w;
    *(float4*)(out1 + (size_t)row * DIM + tid * 4) = o;
    if (out2) *(float4*)(out2 + (size_t)row * DIM + tid * 4) = o;
}

// ---------------- host orchestration ----------------
extern "C" void kernel_launch(void* const* d_in, const int* in_sizes, int n_in,
                              void* d_out, int out_size) {
    const float* mems = (const float*)d_in[0];
    const float* raw  = (const float*)d_in[1];
    /* d_in[2] = attention_mask: analytic, ignored */
    const float* rwb  = (const float*)d_in[3];
    const float* rrb  = (const float*)d_in[4];
    const float* qkvw = (const float*)d_in[5];
    const float* rw   = (const float*)d_in[6];
    const float* ow   = (const float*)d_in[7];
    const float* ln1g = (const float*)d_in[8];
    const float* ln1b = (const float*)d_in[9];
    const float* fw1  = (const float*)d_in[10];
    const float* fb1  = (const float*)d_in[11];
    const float* fw2  = (const float*)d_in[12];
    const float* fb2  = (const float*)d_in[13];
    const float* ln2g = (const float*)d_in[14];
    const float* ln2b = (const float*)d_in[15];
    float* out = (float*)d_out;

    const bool full_out = out_size >= (NLAY + 2) * NE;
    float* out_mems = full_out ? out + NE : nullptr;

    float *wh, *pos, *rh, *av, *tmp, *core, *core2, *ff;
    cudaGetSymbolAddress((void**)&wh,   g_wheads);
    cudaGetSymbolAddress((void**)&pos,  g_pos);
    cudaGetSymbolAddress((void**)&rh,   g_rhead);
    cudaGetSymbolAddress((void**)&av,   g_attnvec);
    cudaGetSymbolAddress((void**)&tmp,  g_tmp);
    cudaGetSymbolAddress((void**)&core, g_core);
    cudaGetSymbolAddress((void**)&core2,g_core2);
    cudaGetSymbolAddress((void**)&ff,   g_ff);

    cudaFuncSetAttribute((const void*)attn_mma_kernel,
                         cudaFuncAttributeMaxDynamicSharedMemorySize, ATTN2_SMEM_BYTES);

    const int C4 = NE / 4;
    const int CB = (C4 + 255) / 256;

    copy_kernel<<<CB, 256>>>(core, raw, C4);
    if (out_mems) copy_kernel<<<CB, 256>>>(out_mems, raw, C4);
    pos_kernel<<<(KLEN * DIM + 255) / 256, 256>>>(pos);

    // upfront batch: all layers' K/V projections (mems only) + all pos GEMMs
    batch_pre_kernel<<<dim3(96, 16), 256>>>(mems, qkvw, pos, rw, wh, rh);

    for (int i = 0; i < NLAY; i++) {
        float* wh_i = wh + i * WHS;
        float* rh_i = rh + i * RHS;

        // q rows: all 3072 cols from core
        mma_gemm<<<dim3(24, 16), 256>>>(
            core, qkvw + (size_t)i * DIM * 3 * DIM,
            wh_i + (size_t)2048 * 3072,
            1024, 1024, 3072, 3072, nullptr, 0);

        attn_mma_kernel<<<dim3(16, 32), 256, ATTN2_SMEM_BYTES>>>(wh_i, rh_i, rwb, rrb, av);

        mma_gemm<<<dim3(8, 16), 256>>>(
            av, ow + (size_t)i * DIM * DIM, tmp,
            1024, 1024, 1024, 1024, nullptr, 0);
        ln_kernel<<<2048, 256>>>(tmp, core, ln1g + i * DIM, ln1b + i * DIM, core2, nullptr);

        mma_gemm<<<dim3(8, 16), 256>>>(
            core2, fw1 + (size_t)i * DIM * DIM, ff,
            1024, 1024, 1024, 1024, fb1 + i * DIM, 1);
        mma_gemm<<<dim3(8, 16), 256>>>(
            ff, fw2 + (size_t)i * DIM * DIM, tmp,
            1024, 1024, 1024, 1024, fb2 + i * DIM, 0);
        float* lnDst = (i == NLAY - 1) ? out : core;
        ln_kernel<<<2048, 256>>>(tmp, core2, ln2g + i * DIM, ln2b + i * DIM, lnDst,
                                 out_mems ? out_mems + (size_t)(i + 1) * NE : nullptr);
    }
}

// round 17
// speedup vs baseline: 1.5442x; 1.0367x over previous
#include <cuda_runtime.h>
#include <cuda_fp16.h>
#include <math.h>
#include <stdint.h>

#define L_Q   1024
#define BSZ   2
#define DIM   1024
#define NHEAD 16
#define DHEAD 64
#define NLAY  4
#define MLEN  1024
#define KLEN  2048
#define NE    (L_Q*BSZ*DIM)   /* 2097152 floats per (L,B,D) slab */
#define WHS   ((size_t)KLEN*BSZ*3*DIM)   /* wheads slab per layer */
#define RHS   ((size_t)KLEN*DIM)         /* rhead slab per layer */

// ---------------- scratch (device globals; no allocation allowed) ----------------
__device__ float g_wheads[NLAY * WHS];   // 201 MB (per-layer)
__device__ float g_pos[(size_t)KLEN*DIM];
__device__ float g_rhead[NLAY * RHS];    // 33.5 MB (per-layer)
__device__ float g_attnvec[NE];
__device__ float g_tmp[NE];
__device__ float g_core[NE];
__device__ float g_core2[NE];
__device__ float g_ff[NE];

// ---------------- simple float4 copy ----------------
__global__ void copy_kernel(float* __restrict__ dst, const float* __restrict__ src, int n4) {
    int i = blockIdx.x * blockDim.x + threadIdx.x;
    if (i < n4) ((float4*)dst)[i] = ((const float4*)src)[i];
}

// ---------------- positional embedding ----------------
__global__ void pos_kernel(float* __restrict__ pos) {
    int idx = blockIdx.x * blockDim.x + threadIdx.x;
    if (idx >= KLEN * DIM) return;
    int j = idx >> 10;
    int i = idx & 1023;
    int t = i & 511;
    float x = (float)(2 * t) * (1.0f / 1024.0f);
    float invf = expf(-x * 9.210340371976184f);
    float arg = (float)(KLEN - 1 - j) * invf;
    pos[idx] = (i < 512) ? sinf(arg) : cosf(arg);
}

// ---------------- helpers ----------------
__device__ __forceinline__ uint32_t pack_h2(float lo, float hi) {
    uint32_t r;
    asm("cvt.rn.f16x2.f32 %0, %1, %2;" : "=r"(r) : "f"(hi), "f"(lo));
    return r;
}
__device__ __forceinline__ uint2 pack4(float4 v) {
    return make_uint2(pack_h2(v.x, v.y), pack_h2(v.z, v.w));
}
__device__ __forceinline__ void mma_f16(float* c, const uint32_t* a, const uint32_t* b) {
    asm volatile(
        "mma.sync.aligned.m16n8k16.row.col.f32.f16.f16.f32 "
        "{%0,%1,%2,%3}, {%4,%5,%6,%7}, {%8,%9}, {%0,%1,%2,%3};"
        : "+f"(c[0]), "+f"(c[1]), "+f"(c[2]), "+f"(c[3])
        : "r"(a[0]), "r"(a[1]), "r"(a[2]), "r"(a[3]), "r"(b[0]), "r"(b[1]));
}

// ---------------- fp16 GEMM body (device function) ----------------
struct GemmSmem {
    uint32_t As[2][2048];
    uint32_t Bs[2][2048];
};

__device__ __forceinline__ void gemm_block(
    GemmSmem* sm,
    const float* __restrict__ A, const float* __restrict__ B, float* __restrict__ C,
    int K, int lda, int ldb, int ldc,
    const float* __restrict__ bias, int relu, int bx, int by)
{
    uint32_t (*As)[2048] = sm->As;
    uint32_t (*Bs)[2048] = sm->Bs;

    const int tid = threadIdx.x;
    const int lane = tid & 31;
    const int w = tid >> 5;
    const int wr = w & 1;
    const int wc = w >> 1;

    const int ar  = tid >> 1;
    const int kh  = tid & 1;
    const int ac  = ((ar >> 1) & 3) + 4 * kh;
    const int abase = (((kh * 8 + (ar >> 4)) * 32 + (ar & 7) * 4) << 2) + ((ar >> 3) & 1);
    const float* Ag = A + (size_t)(by * 128 + ar) * lda + kh * 16;

    const int bl   = lane;
    const int bnn  = bl >> 2;
    const int bppl = bl & 3;
    const int blh  = (bl >> 4) & 1;
    const int nb0  = (tid >> 5) << 1;
    const int bcol0 = bx * 128;

    float acc[4][4][4];
#pragma unroll
    for (int mi = 0; mi < 4; mi++)
#pragma unroll
        for (int ni = 0; ni < 4; ni++)
#pragma unroll
            for (int q = 0; q < 4; q++) acc[mi][ni][q] = 0.f;

    uint32_t paH[8];
    uint32_t pbH[8];

#pragma unroll
    for (int tt = 0; tt < 4; tt++) {
        const float4 v = *(const float4*)(Ag + tt * 4);
        paH[tt * 2 + 0] = pack_h2(v.x, v.y);
        paH[tt * 2 + 1] = pack_h2(v.z, v.w);
    }
#pragma unroll
    for (int j = 0; j < 4; j++) {
        const int ppq4 = (j + blh) & 3;
        const int p = ppq4 * 4 + bppl;
#pragma unroll
        for (int nbi = 0; nbi < 2; nbi++) {
            const int n = (nb0 + nbi) * 8 + bnn;
            pbH[j * 2 + nbi] = pack_h2(B[(size_t)(2 * p) * ldb + bcol0 + n],
                                       B[(size_t)(2 * p + 1) * ldb + bcol0 + n]);
        }
    }
#pragma unroll
    for (int j = 0; j < 8; j++) {
        const int pp2 = (j + ac) & 7;
        As[0][abase + ((pp2 & 3) << 2) + ((pp2 >> 2) << 1)] = paH[pp2];
    }
#pragma unroll
    for (int j = 0; j < 4; j++) {
        const int ppq4 = (j + blh) & 3;
        const int ks = ppq4 >> 1, q = ppq4 & 1;
#pragma unroll
        for (int nbi = 0; nbi < 2; nbi++) {
            const int nb = nb0 + nbi;
            Bs[0][(((ks * 16 + nb) * 32 + bl) << 1) + q] = pbH[j * 2 + nbi];
        }
    }
    __syncthreads();

    const int NT = K >> 5;
    for (int T = 0; T < NT; T++) {
        const int buf = T & 1;
        if (T + 1 < NT) {
            const int off = (T + 1) << 5;
#pragma unroll
            for (int tt = 0; tt < 4; tt++) {
                const float4 v = *(const float4*)(Ag + off + tt * 4);
                paH[tt * 2 + 0] = pack_h2(v.x, v.y);
                paH[tt * 2 + 1] = pack_h2(v.z, v.w);
            }
#pragma unroll
            for (int j = 0; j < 4; j++) {
                const int ppq4 = (j + blh) & 3;
                const int p = ppq4 * 4 + bppl;
#pragma unroll
                for (int nbi = 0; nbi < 2; nbi++) {
                    const int n = (nb0 + nbi) * 8 + bnn;
                    pbH[j * 2 + nbi] = pack_h2(B[(size_t)(off + 2 * p) * ldb + bcol0 + n],
                                               B[(size_t)(off + 2 * p + 1) * ldb + bcol0 + n]);
                }
            }
        }
#pragma unroll
        for (int ks = 0; ks < 2; ks++) {
            uint32_t afr[4][4], bfr[4][2];
#pragma unroll
            for (int mi = 0; mi < 4; mi++) {
                const uint4 v = *(const uint4*)&As[buf][(((ks * 8 + wr * 4 + mi) * 32 + lane) << 2)];
                afr[mi][0] = v.x; afr[mi][1] = v.y; afr[mi][2] = v.z; afr[mi][3] = v.w;
            }
#pragma unroll
            for (int ni = 0; ni < 4; ni++) {
                const uint2 v = *(const uint2*)&Bs[buf][(((ks * 16 + wc * 4 + ni) * 32 + lane) << 1)];
                bfr[ni][0] = v.x; bfr[ni][1] = v.y;
            }
#pragma unroll
            for (int mi = 0; mi < 4; mi++)
#pragma unroll
                for (int ni = 0; ni < 4; ni++)
                    mma_f16(acc[mi][ni], afr[mi], bfr[ni]);
        }
        if (T + 1 < NT) {
            const int nb2 = buf ^ 1;
#pragma unroll
            for (int j = 0; j < 8; j++) {
                const int pp2 = (j + ac) & 7;
                As[nb2][abase + ((pp2 & 3) << 2) + ((pp2 >> 2) << 1)] = paH[pp2];
            }
#pragma unroll
            for (int j = 0; j < 4; j++) {
                const int ppq4 = (j + blh) & 3;
                const int ks = ppq4 >> 1, q = ppq4 & 1;
#pragma unroll
                for (int nbi = 0; nbi < 2; nbi++) {
                    const int nb = nb0 + nbi;
                    Bs[nb2][(((ks * 16 + nb) * 32 + bl) << 1) + q] = pbH[j * 2 + nbi];
                }
            }
        }
        __syncthreads();
    }

    const int g = lane >> 2;
    const int t = lane & 3;
#pragma unroll
    for (int mi = 0; mi < 4; mi++) {
        const int r0 = by * 128 + wr * 64 + mi * 16 + g;
#pragma unroll
        for (int ni = 0; ni < 4; ni++) {
            const int c0 = bx * 128 + wc * 32 + ni * 8 + t * 2;
            float b0 = 0.f, b1 = 0.f;
            if (bias) { b0 = bias[c0]; b1 = bias[c0 + 1]; }
            float2 o0, o1;
            o0.x = acc[mi][ni][0] + b0; o0.y = acc[mi][ni][1] + b1;
            o1.x = acc[mi][ni][2] + b0; o1.y = acc[mi][ni][3] + b1;
            if (relu) {
                o0.x = fmaxf(o0.x, 0.f); o0.y = fmaxf(o0.y, 0.f);
                o1.x = fmaxf(o1.x, 0.f); o1.y = fmaxf(o1.y, 0.f);
            }
            *(float2*)&C[(size_t)r0 * ldc + c0] = o0;
            *(float2*)&C[(size_t)(r0 + 8) * ldc + c0] = o1;
        }
    }
}

// standalone GEMM
__global__ __launch_bounds__(256, 2) void mma_gemm(
    const float* __restrict__ A, const float* __restrict__ B, float* __restrict__ C,
    int K, int lda, int ldb, int ldc,
    const float* __restrict__ bias, int relu)
{
    __shared__ __align__(16) GemmSmem sm;
    gemm_block(&sm, A, B, C, K, lda, ldb, ldc, bias, relu, blockIdx.x, blockIdx.y);
}

// batched upfront launch: all layers' K/V projections + pos GEMMs.
__global__ __launch_bounds__(256, 2) void batch_pre_kernel(
    const float* __restrict__ mems, const float* __restrict__ qkvw,
    const float* __restrict__ pos,  const float* __restrict__ rw,
    float* __restrict__ wh, float* __restrict__ rh)
{
    __shared__ __align__(16) GemmSmem sm;
    const int bx = blockIdx.x, by = blockIdx.y;
    if (bx < 64) {
        const int lay = bx >> 4, bxl = bx & 15;
        gemm_block(&sm,
                   mems + (size_t)lay * NE,
                   qkvw + (size_t)lay * DIM * 3 * DIM + 1024,
                   wh + lay * WHS + 1024,
                   1024, 1024, 3072, 3072, nullptr, 0, bxl, by);
    } else {
        const int b2 = bx - 64;
        const int lay = b2 >> 3, bxl = b2 & 7;
        gemm_block(&sm,
                   pos,
                   rw + (size_t)lay * DIM * DIM,
                   rh + lay * RHS,
                   1024, 1024, 1024, 1024, nullptr, 0, bxl, by);
    }
}

// ---------------- tensor-core fused rel-attention (all fp16 mma) ----------------
// fp16 S/E + fp16 PV (V transposed in smem), pitch-36 half2 tiles, E-band skip,
// R double-buffer.
#define AT_QW 0                     /* 64x36 half2 */
#define AT_QR 2304
#define AT_K  4608
#define AT_R  6912                  /* 2 x 128x36 half2 */
#define AT_VT 16128                 /* 64 dims x 36 keypair half2 */
#define AT_S  18432                 /* 64x68 f32 */
#define AT_E  22784                 /* 64x136 f32 */
#define AT_P  31488                 /* 64x36 half2 */
#define AT_M  33792
#define AT_L  33856
#define AT_A  33920
#define ATTN2_SMEM_FLOATS 33984
#define ATTN2_SMEM_BYTES  (ATTN2_SMEM_FLOATS * 4)

__global__ __launch_bounds__(256) void attn_mma_kernel(
    const float* __restrict__ wh, const float* __restrict__ rh,
    const float* __restrict__ rwb, const float* __restrict__ rrb,
    float* __restrict__ av)
{
    extern __shared__ float smf[];
    uint32_t* sQw = (uint32_t*)(smf + AT_QW);
    uint32_t* sQr = (uint32_t*)(smf + AT_QR);
    uint32_t* sK  = (uint32_t*)(smf + AT_K);
    uint32_t* sR0 = (uint32_t*)(smf + AT_R);
    uint32_t* sR1 = sR0 + 4608;
    uint32_t* sVt = (uint32_t*)(smf + AT_VT);
    float*    sS  = smf + AT_S;
    float*    sE  = smf + AT_E;
    uint32_t* sPh = (uint32_t*)(smf + AT_P);
    float*    sM  = smf + AT_M;
    float*    sL  = smf + AT_L;
    float*    sA  = smf + AT_A;

    const int i0 = (15 - blockIdx.x) << 6;
    const int bi = blockIdx.y >> 4;
    const int hn = blockIdx.y & 15;
    const int tid = threadIdx.x;
    const int lane = tid & 31;
    const int w = tid >> 5;
    const int rb = w >> 1;
    const int ch = w & 1;
    const int g = lane >> 2;
    const int t = lane & 3;
    const int hbase = hn << 6;

    int ebmin = 41 - 16 * rb - 64 * ch;
    ebmin = ebmin <= 0 ? 0 : ((ebmin + 7) >> 3);
    int ebmax = (126 - 16 * rb - 64 * ch) >> 3;
    if (ebmax > 7) ebmax = 7;

    // K staging coords
    const int svr = tid >> 4;
    const int svc = (tid & 15) << 2;
    const int sh2 = (tid & 15) << 1;
    // V transpose staging coords
    const int vj  = tid >> 3;             // keypair 0..31
    const int vdg = tid & 7;              // dgroup (dims 4*vdg and 4*(vdg+8))
    const int vrot = (lane >> 1) & 3;     // STS rotation

    {
        float4 w4 = *(const float4*)&rwb[hbase + svc];
        float4 r4 = *(const float4*)&rrb[hbase + svc];
#pragma unroll
        for (int u = 0; u < 4; u++) {
            const int r = svr + u * 16;
            const size_t base = ((size_t)((MLEN + i0 + r) * BSZ + bi)) * 3072 + hbase + svc;
            float4 q4 = *(const float4*)&wh[base];
            float4 aw = make_float4(q4.x + w4.x, q4.y + w4.y, q4.z + w4.z, q4.w + w4.w);
            float4 ar2 = make_float4(q4.x + r4.x, q4.y + r4.y, q4.z + r4.z, q4.w + r4.w);
            *(uint2*)&sQw[r * 36 + sh2] = pack4(aw);
            *(uint2*)&sQr[r * 36 + sh2] = pack4(ar2);
        }
    }
    if (tid < 64) { sM[tid] = -3e38f; sL[tid] = 0.f; }

    float acc[4][4];
#pragma unroll
    for (int cb = 0; cb < 4; cb++)
#pragma unroll
        for (int q = 0; q < 4; q++) acc[cb][q] = 0.f;

    const int arow0 = (16 * rb + g) * 36;
    const int arow1 = (16 * rb + g + 8) * 36;
    const int nkt = 17 + (i0 >> 6);
    const int C0 = MLEN - 1 - i0 - 63;

    float4 pk[4], pv[4], pr[4];
    // tile-0 prefetch: K rows (svr map), V key-pairs (vj map)
#pragma unroll
    for (int u = 0; u < 4; u++) {
        const int r = svr + u * 16;
        pk[u] = *(const float4*)&wh[((size_t)(r * BSZ + bi)) * 3072 + hbase + svc + 1024];
    }
    {
        const size_t b0 = ((size_t)((2 * vj) * BSZ + bi)) * 3072 + hbase + 2048;
        const size_t b1 = ((size_t)((2 * vj + 1) * BSZ + bi)) * 3072 + hbase + 2048;
        pv[0] = *(const float4*)&wh[b0 + 4 * vdg];
        pv[1] = *(const float4*)&wh[b0 + 4 * (vdg + 8)];
        pv[2] = *(const float4*)&wh[b1 + 4 * vdg];
        pv[3] = *(const float4*)&wh[b1 + 4 * (vdg + 8)];
    }

    for (int kt = 0; kt < nkt; kt++) {
        const int j0 = kt << 6;
        uint32_t* sRn = (kt & 1) ? sR1 : sR0;
        uint32_t* sRo = (kt & 1) ? sR0 : sR1;
        __syncthreads();
        // ---- stage K (half2 rows) and V (transposed half2 keypairs) ----
#pragma unroll
        for (int u = 0; u < 4; u++) {
            const int r = svr + u * 16;
            *(uint2*)&sK[r * 36 + sh2] = pack4(pk[u]);
        }
#pragma unroll
        for (int s = 0; s < 2; s++) {
            const int dgx = vdg + s * 8;
            const float* lo = (const float*)&pv[s];
            const float* hi = (const float*)&pv[s + 2];
#pragma unroll
            for (int ii = 0; ii < 4; ii++) {
                const int i = (ii + vrot) & 3;
                sVt[(4 * dgx + i) * 36 + vj] = pack_h2(lo[i], hi[i]);
            }
        }
        if (kt == 0) {
#pragma unroll
            for (int u = 0; u < 8; u++) {
                const int idx = tid + u * 256;
                if (idx < 2032) {
                    const int r = idx >> 4, c4 = (idx & 15) << 2;
                    int rg = C0 + r;
                    rg = rg < 0 ? 0 : (rg > KLEN - 1 ? KLEN - 1 : rg);
                    const float4 v = *(const float4*)&rh[(size_t)rg * DIM + hbase + c4];
                    *(uint2*)&sRn[r * 36 + ((idx & 15) << 1)] = pack4(v);
                }
            }
        } else {
#pragma unroll
            for (int u = 0; u < 3; u++) {
                const int idx = tid + u * 256;
                if (idx < 567) {
                    const int r = idx / 9, q4 = idx - r * 9;
                    *(uint4*)&sRn[r * 36 + q4 * 4] = *(const uint4*)&sRo[(r + 64) * 36 + q4 * 4];
                }
            }
#pragma unroll
            for (int u = 0; u < 4; u++) {
                const int idx = tid + u * 256;
                const int r = 63 + (idx >> 4);
                *(uint2*)&sRn[r * 36 + ((idx & 15) << 1)] = pack4(pr[u]);
            }
        }
        __syncthreads();

        // ---- prefetch next tile (overlaps mma) ----
        if (kt + 1 < nkt) {
#pragma unroll
            for (int u = 0; u < 4; u++) {
                const int r = svr + u * 16;
                pk[u] = *(const float4*)&wh[((size_t)(((j0 + 64) + r) * BSZ + bi)) * 3072 + hbase + svc + 1024];
            }
            {
                const size_t b0 = ((size_t)((j0 + 64 + 2 * vj) * BSZ + bi)) * 3072 + hbase + 2048;
                const size_t b1 = ((size_t)((j0 + 64 + 2 * vj + 1) * BSZ + bi)) * 3072 + hbase + 2048;
                pv[0] = *(const float4*)&wh[b0 + 4 * vdg];
                pv[1] = *(const float4*)&wh[b0 + 4 * (vdg + 8)];
                pv[2] = *(const float4*)&wh[b1 + 4 * vdg];
                pv[3] = *(const float4*)&wh[b1 + 4 * (vdg + 8)];
            }
            const int rbn = 64 * (kt + 1) + C0;
#pragma unroll
            for (int u = 0; u < 4; u++) {
                const int idx = tid + u * 256;
                int rg = rbn + 63 + (idx >> 4);
                rg = rg < 0 ? 0 : (rg > KLEN - 1 ? KLEN - 1 : rg);
                pr[u] = *(const float4*)&rh[(size_t)rg * DIM + hbase + ((idx & 15) << 2)];
            }
        }

        // ---- S and E via fp16 mma ----
        float Sacc[4][4], Eacc[8][4];
#pragma unroll
        for (int cb = 0; cb < 4; cb++)
#pragma unroll
            for (int q = 0; q < 4; q++) Sacc[cb][q] = 0.f;
#pragma unroll
        for (int eb = 0; eb < 8; eb++)
#pragma unroll
            for (int q = 0; q < 4; q++) Eacc[eb][q] = 0.f;

#pragma unroll
        for (int ks = 0; ks < 4; ks++) {
            const int kb = ks * 8 + t;
            uint32_t aw[4], ar[4];
            aw[0] = sQw[arow0 + kb]; aw[1] = sQw[arow1 + kb];
            aw[2] = sQw[arow0 + kb + 4]; aw[3] = sQw[arow1 + kb + 4];
            ar[0] = sQr[arow0 + kb]; ar[1] = sQr[arow1 + kb];
            ar[2] = sQr[arow0 + kb + 4]; ar[3] = sQr[arow1 + kb + 4];
#pragma unroll
            for (int cb = 0; cb < 4; cb++) {
                const int kr = (8 * (ch * 4 + cb) + g) * 36 + kb;
                uint32_t b[2] = { sK[kr], sK[kr + 4] };
                mma_f16(Sacc[cb], aw, b);
            }
#pragma unroll
            for (int eb = 0; eb < 8; eb++) {
                if (eb >= ebmin && eb <= ebmax) {
                    const int rr = (8 * (ch * 8 + eb) + g) * 36 + kb;
                    uint32_t b[2] = { sRn[rr], sRn[rr + 4] };
                    mma_f16(Eacc[eb], ar, b);
                }
            }
        }
#pragma unroll
        for (int cb = 0; cb < 4; cb++) {
            const int col = 8 * (ch * 4 + cb) + 2 * t;
            *(float2*)&sS[(16 * rb + g) * 68 + col]     = make_float2(Sacc[cb][0], Sacc[cb][1]);
            *(float2*)&sS[(16 * rb + g + 8) * 68 + col] = make_float2(Sacc[cb][2], Sacc[cb][3]);
        }
#pragma unroll
        for (int eb = 0; eb < 8; eb++) {
            if (eb >= ebmin && eb <= ebmax) {
                const int col = 8 * (ch * 8 + eb) + 2 * t;
                *(float2*)&sE[(16 * rb + g) * 136 + col]     = make_float2(Eacc[eb][0], Eacc[eb][1]);
                *(float2*)&sE[(16 * rb + g + 8) * 136 + col] = make_float2(Eacc[eb][2], Eacc[eb][3]);
            }
        }
        __syncthreads();

        // ---- online softmax (P packed as half2 key-pairs) ----
        {
            const int row = w * 8 + g;
            const int qi = i0 + row;
            float sarr[16];
            {
                const float4* srow = (const float4*)&sS[row * 68 + t * 16];
#pragma unroll
                for (int v4 = 0; v4 < 4; v4++) {
                    float4 s4 = srow[v4];
                    sarr[v4 * 4 + 0] = s4.x; sarr[v4 * 4 + 1] = s4.y;
                    sarr[v4 * 4 + 2] = s4.z; sarr[v4 * 4 + 3] = s4.w;
                }
            }
            const int ebase = row * 135 + t * 16 + 63;
            float tmax = -3e38f;
#pragma unroll
            for (int e = 0; e < 16; e++) {
                float vv = (sarr[e] + sE[ebase + e]) * 0.125f;
                if (j0 + t * 16 + e > MLEN + qi) vv = -3e38f;
                sarr[e] = vv;
                tmax = fmaxf(tmax, vv);
            }
            tmax = fmaxf(tmax, __shfl_xor_sync(0xffffffffu, tmax, 1));
            tmax = fmaxf(tmax, __shfl_xor_sync(0xffffffffu, tmax, 2));
            const float mold = sM[row];
            const float mnew = fmaxf(mold, tmax);
            float rsum = 0.f;
            float p[16];
#pragma unroll
            for (int e = 0; e < 16; e++) {
                p[e] = __expf(sarr[e] - mnew);
                rsum += p[e];
            }
            rsum += __shfl_xor_sync(0xffffffffu, rsum, 1);
            rsum += __shfl_xor_sync(0xffffffffu, rsum, 2);
            if (t == 0) {
                const float al = __expf(mold - mnew);
                sM[row] = mnew;
                sA[row] = al;
                sL[row] = sL[row] * al + rsum;
            }
            uint4* pd = (uint4*)&sPh[row * 36 + 8 * t];
            pd[0] = make_uint4(pack_h2(p[0], p[1]), pack_h2(p[2], p[3]),
                               pack_h2(p[4], p[5]), pack_h2(p[6], p[7]));
            pd[1] = make_uint4(pack_h2(p[8], p[9]), pack_h2(p[10], p[11]),
                               pack_h2(p[12], p[13]), pack_h2(p[14], p[15]));
        }
        __syncthreads();

        // ---- rescale + P@V via fp16 mma ----
        {
            const float al0 = sA[16 * rb + g];
            const float al1 = sA[16 * rb + g + 8];
#pragma unroll
            for (int cb = 0; cb < 4; cb++) {
                acc[cb][0] *= al0; acc[cb][1] *= al0;
                acc[cb][2] *= al1; acc[cb][3] *= al1;
            }
            const int prow0 = (16 * rb + g) * 36;
            const int prow1 = (16 * rb + g + 8) * 36;
#pragma unroll
            for (int ks = 0; ks < 4; ks++) {
                const int kb = ks * 8 + t;
                uint32_t a[4] = { sPh[prow0 + kb], sPh[prow1 + kb],
                                  sPh[prow0 + kb + 4], sPh[prow1 + kb + 4] };
#pragma unroll
                for (int cb = 0; cb < 4; cb++) {
                    const int n = (8 * (ch * 4 + cb) + g) * 36;
                    uint32_t b[2] = { sVt[n + kb], sVt[n + kb + 4] };
                    mma_f16(acc[cb], a, b);
                }
            }
        }
    }

    // ---- finalize ----
    const float linv0 = 1.f / sL[16 * rb + g];
    const float linv1 = 1.f / sL[16 * rb + g + 8];
    const int r0 = i0 + 16 * rb + g;
#pragma unroll
    for (int cb = 0; cb < 4; cb++) {
        const int col = hbase + 8 * (ch * 4 + cb) + 2 * t;
        float2 o0, o1;
        o0.x = acc[cb][0] * linv0; o0.y = acc[cb][1] * linv0;
        o1.x = acc[cb][2] * linv1; o1.y = acc[cb][3] * linv1;
        *(float2*)&av[((size_t)(r0 * BSZ + bi)) * DIM + col] = o0;
        *(float2*)&av[((size_t)((r0 + 8) * BSZ + bi)) * DIM + col] = o1;
    }
}

// ---------------- residual + layernorm (row per block) ----------------
__global__ __launch_bounds__(256) void ln_kernel(
    const float* __restrict__ x, const float* __restrict__ res,
    const float* __restrict__ g, const float* __restrict__ b,
    float* __restrict__ out1, float* __restrict__ out2)
{
    const int row = blockIdx.x;
    const int tid = threadIdx.x;
    float4 xv = *(const float4*)(x + (size_t)row * DIM + tid * 4);
    float4 rv = *(const float4*)(res + (size_t)row * DIM + tid * 4);
    float v0 = xv.x + rv.x, v1 = xv.y + rv.y, v2 = xv.z + rv.z, v3 = xv.w + rv.w;
    float s = v0 + v1 + v2 + v3;
    float q = v0 * v0 + v1 * v1 + v2 * v2 + v3 * v3;
#pragma unroll
    for (int off = 16; off > 0; off >>= 1) {
        s += __shfl_xor_sync(0xffffffffu, s, off);
        q += __shfl_xor_sync(0xffffffffu, q, off);
    }
    __shared__ float sb[8], qb[8];
    const int w = tid >> 5, lane = tid & 31;
    if (lane == 0) { sb[w] = s; qb[w] = q; }
    __syncthreads();
    if (w == 0) {
        float s2 = (lane < 8) ? sb[lane] : 0.f;
        float q2 = (lane < 8) ? qb[lane] : 0.f;
#pragma unroll
        for (int off = 4; off > 0; off >>= 1) {
            s2 += __shfl_xor_sync(0xffffffffu, s2, off);
            q2 += __shfl_xor_sync(0xffffffffu, q2, off);
        }
        if (lane == 0) { sb[0] = s2; qb[0] = q2; }
    }
    __syncthreads();
    const float mean = sb[0] * (1.0f / DIM);
    const float var  = qb[0] * (1.0f / DIM) - mean * mean;
    const float rstd = rsqrtf(var + 1e-5f);
    float4 gv = *(const float4*)(g + tid * 4);
    float4 bv = *(const float4*)(b + tid * 4);
    float4 o;
    o.x = (v0 - mean) * rstd * gv.x + bv.x;
    o.y = (v1 - mean) * rstd * gv.y + bv.y;
    o.z = (v2 - mean) * rstd * gv.z + bv.z;
    o.w = (v3 - mean) * rstd * gv.w + bv.w;
    *(float4*)(out1 + (size_t)row * DIM + tid * 4) = o;
    if (out2) *(float4*)(out2 + (size_t)row * DIM + tid * 4) = o;
}

// ---------------- host orchestration ----------------
extern "C" void kernel_launch(void* const* d_in, const int* in_sizes, int n_in,
                              void* d_out, int out_size) {
    const float* mems = (const float*)d_in[0];
    const float* raw  = (const float*)d_in[1];
    /* d_in[2] = attention_mask: analytic, ignored */
    const float* rwb  = (const float*)d_in[3];
    const float* rrb  = (const float*)d_in[4];
    const float* qkvw = (const float*)d_in[5];
    const float* rw   = (const float*)d_in[6];
    const float* ow   = (const float*)d_in[7];
    const float* ln1g = (const float*)d_in[8];
    const float* ln1b = (const float*)d_in[9];
    const float* fw1  = (const float*)d_in[10];
    const float* fb1  = (const float*)d_in[11];
    const float* fw2  = (const float*)d_in[12];
    const float* fb2  = (const float*)d_in[13];
    const float* ln2g = (const float*)d_in[14];
    const float* ln2b = (const float*)d_in[15];
    float* out = (float*)d_out;

    const bool full_out = out_size >= (NLAY + 2) * NE;
    float* out_mems = full_out ? out + NE : nullptr;

    float *wh, *pos, *rh, *av, *tmp, *core, *core2, *ff;
    cudaGetSymbolAddress((void**)&wh,   g_wheads);
    cudaGetSymbolAddress((void**)&pos,  g_pos);
    cudaGetSymbolAddress((void**)&rh,   g_rhead);
    cudaGetSymbolAddress((void**)&av,   g_attnvec);
    cudaGetSymbolAddress((void**)&tmp,  g_tmp);
    cudaGetSymbolAddress((void**)&core, g_core);
    cudaGetSymbolAddress((void**)&core2,g_core2);
    cudaGetSymbolAddress((void**)&ff,   g_ff);

    cudaFuncSetAttribute((const void*)attn_mma_kernel,
                         cudaFuncAttributeMaxDynamicSharedMemorySize, ATTN2_SMEM_BYTES);

    const int C4 = NE / 4;
    const int CB = (C4 + 255) / 256;

    copy_kernel<<<CB, 256>>>(core, raw, C4);
    if (out_mems) copy_kernel<<<CB, 256>>>(out_mems, raw, C4);
    pos_kernel<<<(KLEN * DIM + 255) / 256, 256>>>(pos);

    batch_pre_kernel<<<dim3(96, 16), 256>>>(mems, qkvw, pos, rw, wh, rh);

    for (int i = 0; i < NLAY; i++) {
        float* wh_i = wh + i * WHS;
        float* rh_i = rh + i * RHS;

        mma_gemm<<<dim3(24, 16), 256>>>(
            core, qkvw + (size_t)i * DIM * 3 * DIM,
            wh_i + (size_t)2048 * 3072,
            1024, 1024, 3072, 3072, nullptr, 0);

        attn_mma_kernel<<<dim3(16, 32), 256, ATTN2_SMEM_BYTES>>>(wh_i, rh_i, rwb, rrb, av);

        mma_gemm<<<dim3(8, 16), 256>>>(
            av, ow + (size_t)i * DIM * DIM, tmp,
            1024, 1024, 1024, 1024, nullptr, 0);
        ln_kernel<<<2048, 256>>>(tmp, core, ln1g + i * DIM, ln1b + i * DIM, core2, nullptr);

        mma_gemm<<<dim3(8, 16), 256>>>(
            core2, fw1 + (size_t)i * DIM * DIM, ff,
            1024, 1024, 1024, 1024, fb1 + i * DIM, 1);
        mma_gemm<<<dim3(8, 16), 256>>>(
            ff, fw2 + (size_t)i * DIM * DIM, tmp,
            1024, 1024, 1024, 1024, fb2 + i * DIM, 0);
        float* lnDst = (i == NLAY - 1) ? out : core;
        ln_kernel<<<2048, 256>>>(tmp, core2, ln2g + i * DIM, ln2b + i * DIM, lnDst,
                                 out_mems ? out_mems + (size_t)(i + 1) * NE : nullptr);
    }
}